// round 9
// baseline (speedup 1.0000x reference)
#include <cuda_runtime.h>
#include <cuda_bf16.h>
#include <math.h>
#include <stdint.h>

// Problem constants (ContTimeLSTM_66623532695635)
#define Bsz 128
#define Lseq 512
#define Iin 256
#define Dh 512
#define ND 3584          // 7*D
#define FIN 768          // I + D
#define BD (Bsz*Dh)      // 65536

#define GRID_R 128       // persistent recur blocks
#define NTR 512          // 16 warps: wm = w&3 (m16 group), wk = w>>2 (k quarter)

// ---------------- device scratch ----------------
__device__ float g_xp[(size_t)Lseq * Bsz * ND];        // ~940 MB, [t][b][n]
__device__ uint32_t g_Hsplit[2][BD];                   // packed bf16 (hi | lo<<16)
__device__ uint32_t g_xpack[(size_t)Bsz * Lseq * Iin]; // packed masked x
#define WFRAG_PLANE (28 * 16384)
__device__ uint32_t g_wfrag[2 * WFRAG_PLANE];          // W x-part fragments
__device__ float g_proj0[ND];
__device__ __align__(256) unsigned g_bar2[64];         // [0]: half 0, [32]: half 1

__device__ __forceinline__ float sigf(float x) { return 1.0f / (1.0f + expf(-x)); }
__device__ __forceinline__ float softplusf(float x) {
    return (x > 0.0f) ? (x + log1pf(expf(-x))) : log1pf(expf(x));
}
__device__ __forceinline__ unsigned ld_acq(unsigned* p) {
    unsigned v;
    asm volatile("ld.acquire.gpu.u32 %0, [%1];" : "=r"(v) : "l"(p) : "memory");
    return v;
}
__device__ __forceinline__ void red_rel_add1(unsigned* p) {
    asm volatile("red.release.gpu.global.add.u32 [%0], 1;" :: "l"(p) : "memory");
}
__device__ __forceinline__ uint32_t prmt_(uint32_t a, uint32_t b, uint32_t s) {
    uint32_t r;
    asm("prmt.b32 %0, %1, %2, %3;" : "=r"(r) : "r"(a), "r"(b), "r"(s));
    return r;
}
__device__ __forceinline__ uint32_t pack_hl(float v) {
    __nv_bfloat16 hi = __float2bfloat16(v);
    __nv_bfloat16 lo = __float2bfloat16(v - __bfloat162float(hi));
    return ((uint32_t)__bfloat16_as_ushort(lo) << 16) | __bfloat16_as_ushort(hi);
}
__device__ __forceinline__ uint32_t pack2bf(__nv_bfloat16 a, __nv_bfloat16 b) {
    return ((uint32_t)__bfloat16_as_ushort(b) << 16) | __bfloat16_as_ushort(a);
}

#define MMA_BF16(d, a, b0, b1) \
    asm volatile("mma.sync.aligned.m16n8k16.row.col.f32.bf16.bf16.f32 " \
        "{%0,%1,%2,%3}, {%4,%5,%6,%7}, {%8,%9}, {%0,%1,%2,%3};" \
        : "+f"((d)[0]), "+f"((d)[1]), "+f"((d)[2]), "+f"((d)[3]) \
        : "r"((a)[0]), "r"((a)[1]), "r"((a)[2]), "r"((a)[3]), "r"(b0), "r"(b1))

// ---------------- launch 1: reset barriers + proj0 ----------------
__global__ void prep_kernel(const float* __restrict__ bos,
                            const float* __restrict__ W,
                            const float* __restrict__ bias) {
    int n = blockIdx.x * blockDim.x + threadIdx.x;
    if (n == 0) { g_bar2[0] = 0u; g_bar2[32] = 0u; }
    if (n >= ND) return;
    const float* wrow = W + (size_t)n * FIN;
    float acc = bias[n];
    #pragma unroll 8
    for (int i = 0; i < Iin; i++) acc += bos[i] * wrow[i];
    g_proj0[n] = acc;
}

// ---------------- launch 2: pack x (masked) + W x-part fragments ----------------
#define XN (Bsz * Lseq * Iin)          // 16,777,216
#define WN (28 * 16 * 16 * 32)         // 229,376
__global__ void pack_kernel(const float* __restrict__ x,
                            const int* __restrict__ sl,
                            const float* __restrict__ W) {
    int idx = blockIdx.x * blockDim.x + threadIdx.x;
    if (idx < XN) {
        int row = idx >> 8;
        int i = idx & 255;
        int t = row >> 7;
        int b = row & 127;
        float v = (t < __ldg(sl + b)) ? x[((size_t)b * Lseq + t) * Iin + i] : 0.0f;
        g_xpack[idx] = pack_hl(v);
        return;
    }
    int e = idx - XN;
    if (e >= WN) return;
    int lane = e & 31;
    int nt = (e >> 5) & 15;
    int ks = (e >> 9) & 15;
    int nb = e >> 13;
    int gg = lane >> 2, tt = lane & 3;
    int n = nb * 128 + nt * 8 + gg;
    const float* wr = W + (size_t)n * FIN + ks * 16 + tt * 2;
    float w0 = wr[0], w1 = wr[1], w2 = wr[8], w3 = wr[9];
    __nv_bfloat16 h0 = __float2bfloat16(w0), h1 = __float2bfloat16(w1);
    __nv_bfloat16 h2 = __float2bfloat16(w2), h3 = __float2bfloat16(w3);
    __nv_bfloat16 l0 = __float2bfloat16(w0 - __bfloat162float(h0));
    __nv_bfloat16 l1 = __float2bfloat16(w1 - __bfloat162float(h1));
    __nv_bfloat16 l2 = __float2bfloat16(w2 - __bfloat162float(h2));
    __nv_bfloat16 l3 = __float2bfloat16(w3 - __bfloat162float(h3));
    size_t base = (size_t)e * 2;
    g_wfrag[base] = pack2bf(h0, h1);
    g_wfrag[base + 1] = pack2bf(h2, h3);
    g_wfrag[WFRAG_PLANE + base] = pack2bf(l0, l1);
    g_wfrag[WFRAG_PLANE + base + 1] = pack2bf(l2, l3);
}

// ---------------- launch 3: XP = mask(x) @ Wx^T + bias via HMMA ----------------
__global__ __launch_bounds__(256, 1)
void xproj_hmma_kernel(const float* __restrict__ bias) {
    extern __shared__ uint32_t sW[];   // 32768 u32
    const int tid = threadIdx.x;
    const int w = tid >> 5, lane = tid & 31;
    const int g = lane >> 2, tq = lane & 3;
    const int nb = blockIdx.x, mb = blockIdx.y;

    #pragma unroll
    for (int p = 0; p < 2; p++) {
        const uint4* src = (const uint4*)(g_wfrag + (size_t)p * WFRAG_PLANE + nb * 16384);
        uint4* dst = (uint4*)(sW + p * 16384);
        #pragma unroll
        for (int i = 0; i < 16; i++) dst[tid + i * 256] = src[tid + i * 256];
    }
    __syncthreads();

    const int r0 = mb * 128 + w * 16 + g;

    float acc[16][4];
    #pragma unroll
    for (int nt = 0; nt < 16; nt++) {
        int n = nb * 128 + nt * 8 + tq * 2;
        float b0 = __ldg(bias + n), b1 = __ldg(bias + n + 1);
        acc[nt][0] = b0; acc[nt][1] = b1; acc[nt][2] = b0; acc[nt][3] = b1;
    }

    uint2 ring[2][4];
    #pragma unroll
    for (int p = 0; p < 2; p++) {
        int kb = p * 16 + tq * 2;
        ring[p][0] = *(const uint2*)(g_xpack + (size_t)r0 * Iin + kb);
        ring[p][1] = *(const uint2*)(g_xpack + (size_t)(r0 + 8) * Iin + kb);
        ring[p][2] = *(const uint2*)(g_xpack + (size_t)r0 * Iin + kb + 8);
        ring[p][3] = *(const uint2*)(g_xpack + (size_t)(r0 + 8) * Iin + kb + 8);
    }

    #pragma unroll 2
    for (int ks = 0; ks < 16; ks++) {
        int slot = ks & 1;
        uint32_t ah[4], al[4];
        #pragma unroll
        for (int q = 0; q < 4; q++) {
            ah[q] = prmt_(ring[slot][q].x, ring[slot][q].y, 0x5410);
            al[q] = prmt_(ring[slot][q].x, ring[slot][q].y, 0x7632);
        }
        if (ks + 2 < 16) {
            int kb = (ks + 2) * 16 + tq * 2;
            ring[slot][0] = *(const uint2*)(g_xpack + (size_t)r0 * Iin + kb);
            ring[slot][1] = *(const uint2*)(g_xpack + (size_t)(r0 + 8) * Iin + kb);
            ring[slot][2] = *(const uint2*)(g_xpack + (size_t)r0 * Iin + kb + 8);
            ring[slot][3] = *(const uint2*)(g_xpack + (size_t)(r0 + 8) * Iin + kb + 8);
        }
        uint32_t bhx[16][2];
        #pragma unroll
        for (int nt = 0; nt < 16; nt++) {
            uint2 vh = *(const uint2*)(sW + ((ks * 16 + nt) * 32 + lane) * 2);
            bhx[nt][0] = vh.x; bhx[nt][1] = vh.y;
            MMA_BF16(acc[nt], ah, vh.x, vh.y);
        }
        #pragma unroll
        for (int nt = 0; nt < 16; nt++)
            MMA_BF16(acc[nt], al, bhx[nt][0], bhx[nt][1]);
        #pragma unroll
        for (int nt = 0; nt < 16; nt++) {
            uint2 vl = *(const uint2*)(sW + 16384 + ((ks * 16 + nt) * 32 + lane) * 2);
            MMA_BF16(acc[nt], ah, vl.x, vl.y);
        }
    }

    #pragma unroll
    for (int nt = 0; nt < 16; nt++) {
        int n = nb * 128 + nt * 8 + tq * 2;
        *(float2*)&g_xp[(size_t)r0 * ND + n] = make_float2(acc[nt][0], acc[nt][1]);
        *(float2*)&g_xp[(size_t)(r0 + 8) * ND + n] = make_float2(acc[nt][2], acc[nt][3]);
    }
}

// ================= launch 4: persistent recurrence =================
// 128 blocks = 64 d-chunks x 2 batch-halves. 16 warps = 4 wm (m16) x 4 wk (K=128).
// All wk planes -> sRed; epilogue distributed: 1 (b,d) pair per thread.
#define NFRAG 224                    // 32 ks * 7 nt
#define SB_U32 (NFRAG * 32 * 4)      // 28672 u32 = 114688 B
#define RSTRIDE 58                   // floats per sRed row (padded)
#define SRED_FLOATS (4 * 64 * RSTRIDE)
#define SMEM_RECUR (SB_U32 * 4 + SRED_FLOATS * 4)

__global__ __launch_bounds__(NTR, 1)
void recur_kernel(const float* __restrict__ W,
                  const float* __restrict__ dt,
                  const int* __restrict__ sl,
                  float* __restrict__ out_h,
                  float* __restrict__ out_final) {
    extern __shared__ uint32_t sB[];
    float* sRed = (float*)(sB + SB_U32);

    const int tid = threadIdx.x;
    const int w = tid >> 5;
    const int lane = tid & 31;
    const int g = lane >> 2;
    const int tq = lane & 3;
    const int wm = w & 3;            // m16 group (0..3)
    const int wk = w >> 2;           // k quarter (0..3)
    const int dn = blockIdx.x >> 1;
    const int bh = blockIdx.x & 1;
    unsigned* barp = &g_bar2[bh * 32];

    // epilogue ownership: 1 (b,d) pair per thread
    const int er = tid & 63;         // row in half
    const int ej = tid >> 6;         // d within chunk (0..7)
    const int eb = bh * 64 + er;     // batch row
    const int ed = dn * 8 + ej;      // global d

    // ---- pack W h-part fragments (interleaved hi/lo) ----
    for (int e = tid; e < NFRAG * 32; e += NTR) {
        int f = e >> 5;
        int l = e & 31;
        int ks = f / 7, nt = f % 7;
        int gg = l >> 2, tt = l & 3;
        int n = nt * Dh + dn * 8 + gg;
        const float* wr = W + (size_t)n * FIN + Iin + ks * 16;
        float w0 = wr[tt * 2], w1 = wr[tt * 2 + 1];
        float w2 = wr[tt * 2 + 8], w3 = wr[tt * 2 + 9];
        __nv_bfloat16 h0 = __float2bfloat16(w0), h1 = __float2bfloat16(w1);
        __nv_bfloat16 h2 = __float2bfloat16(w2), h3 = __float2bfloat16(w3);
        __nv_bfloat16 l0 = __float2bfloat16(w0 - __bfloat162float(h0));
        __nv_bfloat16 l1 = __float2bfloat16(w1 - __bfloat162float(h1));
        __nv_bfloat16 l2 = __float2bfloat16(w2 - __bfloat162float(h2));
        __nv_bfloat16 l3 = __float2bfloat16(w3 - __bfloat162float(h3));
        uint32_t* p = sB + (size_t)e * 4;
        p[0] = pack2bf(h0, h1);
        p[1] = pack2bf(h2, h3);
        p[2] = pack2bf(l0, l1);
        p[3] = pack2bf(l2, l3);
    }

    // MMA rows for this warp
    int rows[2];
    rows[0] = bh * 64 + wm * 16 + g;
    rows[1] = rows[0] + 8;

    // ---- per-thread state init (t=0) ----
    const int len = sl[eb];
    float stC, stCe;
    {
        float p0 = g_proj0[0 * Dh + ed];
        float p2 = g_proj0[2 * Dh + ed];
        float p4 = g_proj0[4 * Dh + ed];
        float p5 = g_proj0[5 * Dh + ed];
        float p6 = g_proj0[6 * Dh + ed];
        float z   = tanhf(p5);
        float cs0 = sigf(p0) * z;
        float ce0 = sigf(p2) * z;
        float o0  = sigf(p4);
        float dn0 = softplusf(p6);
        float dtv = dt[eb * Lseq + 0];
        float c = ce0 + (cs0 - ce0) * expf(-dn0 * dtv);
        float h = o0 * tanhf(c);
        stC = c; stCe = ce0;
        out_h[((size_t)eb * Lseq + 0) * Dh + ed] = h;
        g_Hsplit[0][eb * Dh + ed] = pack_hl(h);
    }

    // prefetch XP[0] + dt[1]
    float xp[7];
    #pragma unroll
    for (int nt = 0; nt < 7; nt++)
        xp[nt] = g_xp[((size_t)0 * Bsz + eb) * ND + nt * Dh + ed];
    float dtn = dt[eb * Lseq + 1];

    __syncthreads();                         // sB + h0 stores done block-wide
    if (tid == 0) {
        asm volatile("membar.gl;" ::: "memory");
        red_rel_add1(barp);                  // 1 arrival/block -> 64/half
    }
    unsigned tgt = 64;
    if (tid == 0) { while (ld_acq(barp) < tgt) {} }
    __syncthreads();

    const int kbase = wk * 128;              // u32 (d) offset of this k-quarter

    for (int t = 0; t < Lseq; t++) {
        const uint32_t* Hs = g_Hsplit[t & 1];

        float acc[7][4];
        #pragma unroll
        for (int nt = 0; nt < 7; nt++)
            #pragma unroll
            for (int ci = 0; ci < 4; ci++) acc[nt][ci] = 0.0f;

        // ring-4 A prefetch
        uint2 ring[4][4];
        #pragma unroll
        for (int p = 0; p < 4; p++) {
            int kb = kbase + p * 16 + tq * 2;
            ring[p][0] = *(const uint2*)(Hs + rows[0] * Dh + kb);
            ring[p][1] = *(const uint2*)(Hs + rows[1] * Dh + kb);
            ring[p][2] = *(const uint2*)(Hs + rows[0] * Dh + kb + 8);
            ring[p][3] = *(const uint2*)(Hs + rows[1] * Dh + kb + 8);
        }

        #pragma unroll 4
        for (int ks = 0; ks < 8; ks++) {
            int slot = ks & 3;
            uint32_t ah[4], al[4];
            #pragma unroll
            for (int q = 0; q < 4; q++) {
                ah[q] = prmt_(ring[slot][q].x, ring[slot][q].y, 0x5410);
                al[q] = prmt_(ring[slot][q].x, ring[slot][q].y, 0x7632);
            }
            if (ks + 4 < 8) {
                int kb = kbase + (ks + 4) * 16 + tq * 2;
                ring[slot][0] = *(const uint2*)(Hs + rows[0] * Dh + kb);
                ring[slot][1] = *(const uint2*)(Hs + rows[1] * Dh + kb);
                ring[slot][2] = *(const uint2*)(Hs + rows[0] * Dh + kb + 8);
                ring[slot][3] = *(const uint2*)(Hs + rows[1] * Dh + kb + 8);
            }
            int gks = wk * 8 + ks;
            uint4 bv[7];
            #pragma unroll
            for (int nt = 0; nt < 7; nt++)
                bv[nt] = *(const uint4*)(sB + (size_t)((gks * 7 + nt) * 32 + lane) * 4);
            #pragma unroll
            for (int nt = 0; nt < 7; nt++)
                MMA_BF16(acc[nt], ah, bv[nt].x, bv[nt].y);
            #pragma unroll
            for (int nt = 0; nt < 7; nt++)
                MMA_BF16(acc[nt], al, bv[nt].x, bv[nt].y);
            #pragma unroll
            for (int nt = 0; nt < 7; nt++)
                MMA_BF16(acc[nt], ah, bv[nt].z, bv[nt].w);
        }

        // all wk write their plane
        #pragma unroll
        for (int rh = 0; rh < 2; rh++) {
            int row = wm * 16 + rh * 8 + g;
            float* rp = sRed + (size_t)(wk * 64 + row) * RSTRIDE;
            #pragma unroll
            for (int nt = 0; nt < 7; nt++)
                *(float2*)(rp + nt * 8 + tq * 2) =
                    make_float2(acc[nt][rh * 2], acc[nt][rh * 2 + 1]);
        }
        __syncthreads();                     // sRed complete

        // ---- distributed epilogue: 1 (b,d) pair per thread ----
        {
            float pj[7];
            #pragma unroll
            for (int nt = 0; nt < 7; nt++) pj[nt] = xp[nt];
            #pragma unroll
            for (int q = 0; q < 4; q++) {
                const float* rp = sRed + (size_t)(q * 64 + er) * RSTRIDE + ej;
                #pragma unroll
                for (int nt = 0; nt < 7; nt++) pj[nt] += rp[nt * 8];
            }
            float i_g  = sigf(pj[0]);
            float f_g  = sigf(pj[1]);
            float ie_g = sigf(pj[2]);
            float fe_g = sigf(pj[3]);
            float o_n  = sigf(pj[4]);
            float z    = tanhf(pj[5]);
            float d_n  = softplusf(pj[6]);
            float cs_n = f_g * stC + i_g * z;
            float ce_n = fe_g * stCe + ie_g * z;
            if (t == len - 1) {
                float* f = out_final + (size_t)eb * 4 * Dh + ed;
                f[0 * Dh] = o_n;
                f[1 * Dh] = cs_n;
                f[2 * Dh] = ce_n;
                f[3 * Dh] = d_n;
            }
            float dtv = ((t + 1) < len) ? dtn : 0.0f;
            float cn = ce_n + (cs_n - ce_n) * expf(-d_n * dtv);
            float h = o_n * tanhf(cn);
            stC = cn; stCe = ce_n;
            if (t + 1 < Lseq) {
                out_h[((size_t)eb * Lseq + (t + 1)) * Dh + ed] = h;
                g_Hsplit[(t + 1) & 1][eb * Dh + ed] = pack_hl(h);
            }
        }

        if (t + 1 < Lseq) {
            // prefetch XP[t+1] + dt[t+2] (hidden behind barrier wait)
            #pragma unroll
            for (int nt = 0; nt < 7; nt++)
                xp[nt] = g_xp[((size_t)(t + 1) * Bsz + eb) * ND + nt * Dh + ed];
            dtn = (t + 2 < Lseq) ? dt[eb * Lseq + t + 2] : 0.0f;

            __syncthreads();                 // h stores + sRed reads complete
            if (tid == 0) {
                asm volatile("membar.gl;" ::: "memory");
                red_rel_add1(barp);          // publish h_{t+1}
            }
            tgt += 64;
            if (tid == 0) { while (ld_acq(barp) < tgt) {} }
            __syncthreads();
        }
    }
}

// ---------------- launch ----------------
extern "C" void kernel_launch(void* const* d_in, const int* in_sizes, int n_in,
                              void* d_out, int out_size) {
    const float* x    = (const float*)d_in[0];   // (B,L,I)
    const float* dt   = (const float*)d_in[1];   // (B,L)
    const int*   sl   = (const int*)  d_in[2];   // (B,)
    const float* bos  = (const float*)d_in[3];   // (I,)
    const float* W    = (const float*)d_in[4];   // (7D, I+D)
    const float* bias = (const float*)d_in[5];   // (7D,)
    float* out = (float*)d_out;
    float* out_final = out + (size_t)Bsz * Lseq * Dh;

    cudaFuncSetAttribute(recur_kernel, cudaFuncAttributeMaxDynamicSharedMemorySize,
                         SMEM_RECUR);
    cudaFuncSetAttribute(xproj_hmma_kernel, cudaFuncAttributeMaxDynamicSharedMemorySize,
                         32768 * 4);

    prep_kernel<<<(ND + 255) / 256, 256>>>(bos, W, bias);
    pack_kernel<<<(XN + WN + 255) / 256, 256>>>(x, sl, W);
    xproj_hmma_kernel<<<dim3(28, 512), 256, 32768 * 4>>>(bias);
    recur_kernel<<<GRID_R, NTR, SMEM_RECUR>>>(W, dt, sl, out, out_final);
}

// round 10
// speedup vs baseline: 1.2491x; 1.2491x over previous
#include <cuda_runtime.h>
#include <cuda_bf16.h>
#include <math.h>
#include <stdint.h>

// Problem constants (ContTimeLSTM_66623532695635)
#define Bsz 128
#define Lseq 512
#define Iin 256
#define Dh 512
#define ND 3584          // 7*D
#define FIN 768          // I + D
#define BD (Bsz*Dh)      // 65536

#define GRID_R 128       // persistent recur blocks
#define NTR 512          // 16 warps: wm = w&3 (m16 group), wk = w>>2 (k quarter)

// ---------------- device scratch ----------------
// XP2 layout: [t][dn(64)][b(128)][gate(7)*8 + j]  -> per-block contiguous 14KB/step
__device__ float g_xp2[(size_t)Lseq * 64 * Bsz * 56];
__device__ uint32_t g_Hsplit[2][BD];                   // packed bf16 (hi | lo<<16)
__device__ uint32_t g_xpack[(size_t)Bsz * Lseq * Iin]; // packed masked x
#define WFRAG_PLANE (28 * 16384)
__device__ uint32_t g_wfrag[2 * WFRAG_PLANE];          // W x-part fragments
__device__ float g_proj0[ND];
__device__ __align__(256) unsigned g_bar2[64];         // [0]: half 0, [32]: half 1

__device__ __forceinline__ float sigf(float x) { return 1.0f / (1.0f + expf(-x)); }
__device__ __forceinline__ float softplusf(float x) {
    return (x > 0.0f) ? (x + log1pf(expf(-x))) : log1pf(expf(x));
}
__device__ __forceinline__ unsigned ld_acq(unsigned* p) {
    unsigned v;
    asm volatile("ld.acquire.gpu.u32 %0, [%1];" : "=r"(v) : "l"(p) : "memory");
    return v;
}
__device__ __forceinline__ void red_rel_add1(unsigned* p) {
    asm volatile("red.release.gpu.global.add.u32 [%0], 1;" :: "l"(p) : "memory");
}
__device__ __forceinline__ uint32_t prmt_(uint32_t a, uint32_t b, uint32_t s) {
    uint32_t r;
    asm("prmt.b32 %0, %1, %2, %3;" : "=r"(r) : "r"(a), "r"(b), "r"(s));
    return r;
}
__device__ __forceinline__ uint32_t pack_hl(float v) {
    __nv_bfloat16 hi = __float2bfloat16(v);
    __nv_bfloat16 lo = __float2bfloat16(v - __bfloat162float(hi));
    return ((uint32_t)__bfloat16_as_ushort(lo) << 16) | __bfloat16_as_ushort(hi);
}
__device__ __forceinline__ uint32_t pack2bf(__nv_bfloat16 a, __nv_bfloat16 b) {
    return ((uint32_t)__bfloat16_as_ushort(b) << 16) | __bfloat16_as_ushort(a);
}

#define MMA_BF16(d, a, b0, b1) \
    asm volatile("mma.sync.aligned.m16n8k16.row.col.f32.bf16.bf16.f32 " \
        "{%0,%1,%2,%3}, {%4,%5,%6,%7}, {%8,%9}, {%0,%1,%2,%3};" \
        : "+f"((d)[0]), "+f"((d)[1]), "+f"((d)[2]), "+f"((d)[3]) \
        : "r"((a)[0]), "r"((a)[1]), "r"((a)[2]), "r"((a)[3]), "r"(b0), "r"(b1))

// ---------------- launch 1: reset barriers + proj0 ----------------
__global__ void prep_kernel(const float* __restrict__ bos,
                            const float* __restrict__ W,
                            const float* __restrict__ bias) {
    int n = blockIdx.x * blockDim.x + threadIdx.x;
    if (n == 0) { g_bar2[0] = 0u; g_bar2[32] = 0u; }
    if (n >= ND) return;
    const float* wrow = W + (size_t)n * FIN;
    float acc = bias[n];
    #pragma unroll 8
    for (int i = 0; i < Iin; i++) acc += bos[i] * wrow[i];
    g_proj0[n] = acc;
}

// ---------------- launch 2: pack x (masked) + W x-part fragments ----------------
#define XN (Bsz * Lseq * Iin)          // 16,777,216
#define WN (28 * 16 * 16 * 32)         // 229,376
__global__ void pack_kernel(const float* __restrict__ x,
                            const int* __restrict__ sl,
                            const float* __restrict__ W) {
    int idx = blockIdx.x * blockDim.x + threadIdx.x;
    if (idx < XN) {
        int row = idx >> 8;
        int i = idx & 255;
        int t = row >> 7;
        int b = row & 127;
        float v = (t < __ldg(sl + b)) ? x[((size_t)b * Lseq + t) * Iin + i] : 0.0f;
        g_xpack[idx] = pack_hl(v);
        return;
    }
    int e = idx - XN;
    if (e >= WN) return;
    int lane = e & 31;
    int nt = (e >> 5) & 15;
    int ks = (e >> 9) & 15;
    int nb = e >> 13;
    int gg = lane >> 2, tt = lane & 3;
    int n = nb * 128 + nt * 8 + gg;
    const float* wr = W + (size_t)n * FIN + ks * 16 + tt * 2;
    float w0 = wr[0], w1 = wr[1], w2 = wr[8], w3 = wr[9];
    __nv_bfloat16 h0 = __float2bfloat16(w0), h1 = __float2bfloat16(w1);
    __nv_bfloat16 h2 = __float2bfloat16(w2), h3 = __float2bfloat16(w3);
    __nv_bfloat16 l0 = __float2bfloat16(w0 - __bfloat162float(h0));
    __nv_bfloat16 l1 = __float2bfloat16(w1 - __bfloat162float(h1));
    __nv_bfloat16 l2 = __float2bfloat16(w2 - __bfloat162float(h2));
    __nv_bfloat16 l3 = __float2bfloat16(w3 - __bfloat162float(h3));
    size_t base = (size_t)e * 2;
    g_wfrag[base] = pack2bf(h0, h1);
    g_wfrag[base + 1] = pack2bf(h2, h3);
    g_wfrag[WFRAG_PLANE + base] = pack2bf(l0, l1);
    g_wfrag[WFRAG_PLANE + base + 1] = pack2bf(l2, l3);
}

// ---------------- launch 3: XP = mask(x) @ Wx^T + bias via HMMA ----------------
__global__ __launch_bounds__(256, 1)
void xproj_hmma_kernel(const float* __restrict__ bias) {
    extern __shared__ uint32_t sW[];   // 32768 u32
    const int tid = threadIdx.x;
    const int w = tid >> 5, lane = tid & 31;
    const int g = lane >> 2, tq = lane & 3;
    const int nb = blockIdx.x, mb = blockIdx.y;

    #pragma unroll
    for (int p = 0; p < 2; p++) {
        const uint4* src = (const uint4*)(g_wfrag + (size_t)p * WFRAG_PLANE + nb * 16384);
        uint4* dst = (uint4*)(sW + p * 16384);
        #pragma unroll
        for (int i = 0; i < 16; i++) dst[tid + i * 256] = src[tid + i * 256];
    }
    __syncthreads();

    const int r0 = mb * 128 + w * 16 + g;

    float acc[16][4];
    #pragma unroll
    for (int nt = 0; nt < 16; nt++) {
        int n = nb * 128 + nt * 8 + tq * 2;
        float b0 = __ldg(bias + n), b1 = __ldg(bias + n + 1);
        acc[nt][0] = b0; acc[nt][1] = b1; acc[nt][2] = b0; acc[nt][3] = b1;
    }

    uint2 ring[2][4];
    #pragma unroll
    for (int p = 0; p < 2; p++) {
        int kb = p * 16 + tq * 2;
        ring[p][0] = *(const uint2*)(g_xpack + (size_t)r0 * Iin + kb);
        ring[p][1] = *(const uint2*)(g_xpack + (size_t)(r0 + 8) * Iin + kb);
        ring[p][2] = *(const uint2*)(g_xpack + (size_t)r0 * Iin + kb + 8);
        ring[p][3] = *(const uint2*)(g_xpack + (size_t)(r0 + 8) * Iin + kb + 8);
    }

    #pragma unroll 2
    for (int ks = 0; ks < 16; ks++) {
        int slot = ks & 1;
        uint32_t ah[4], al[4];
        #pragma unroll
        for (int q = 0; q < 4; q++) {
            ah[q] = prmt_(ring[slot][q].x, ring[slot][q].y, 0x5410);
            al[q] = prmt_(ring[slot][q].x, ring[slot][q].y, 0x7632);
        }
        if (ks + 2 < 16) {
            int kb = (ks + 2) * 16 + tq * 2;
            ring[slot][0] = *(const uint2*)(g_xpack + (size_t)r0 * Iin + kb);
            ring[slot][1] = *(const uint2*)(g_xpack + (size_t)(r0 + 8) * Iin + kb);
            ring[slot][2] = *(const uint2*)(g_xpack + (size_t)r0 * Iin + kb + 8);
            ring[slot][3] = *(const uint2*)(g_xpack + (size_t)(r0 + 8) * Iin + kb + 8);
        }
        uint32_t bhx[16][2];
        #pragma unroll
        for (int nt = 0; nt < 16; nt++) {
            uint2 vh = *(const uint2*)(sW + ((ks * 16 + nt) * 32 + lane) * 2);
            bhx[nt][0] = vh.x; bhx[nt][1] = vh.y;
            MMA_BF16(acc[nt], ah, vh.x, vh.y);
        }
        #pragma unroll
        for (int nt = 0; nt < 16; nt++)
            MMA_BF16(acc[nt], al, bhx[nt][0], bhx[nt][1]);
        #pragma unroll
        for (int nt = 0; nt < 16; nt++) {
            uint2 vl = *(const uint2*)(sW + 16384 + ((ks * 16 + nt) * 32 + lane) * 2);
            MMA_BF16(acc[nt], ah, vl.x, vl.y);
        }
    }

    // epilogue: write into XP2 layout [t][dn][b][gate*8 + j]
    const int tt0 = r0 >> 7;           // timestep of this tile (same for r0 and r0+8)
    const int b0 = r0 & 127;
    #pragma unroll
    for (int nt = 0; nt < 16; nt++) {
        int n = nb * 128 + nt * 8 + tq * 2;
        int gate = n >> 9;
        int dloc = n & 511;
        int dnx = dloc >> 3;
        size_t base = (((size_t)tt0 * 64 + dnx) * 128);
        size_t off = gate * 8 + (dloc & 7);
        *(float2*)&g_xp2[(base + b0) * 56 + off]     = make_float2(acc[nt][0], acc[nt][1]);
        *(float2*)&g_xp2[(base + b0 + 8) * 56 + off] = make_float2(acc[nt][2], acc[nt][3]);
    }
}

// ================= launch 4: persistent recurrence =================
// 128 blocks = 64 d-chunks x 2 batch-halves. 16 warps = 4 wm (m16) x 4 wk (K=128).
// wk0 warps own epilogue (R8 structure). Single barrier arrival per block.
#define NFRAG 224                    // 32 ks * 7 nt
#define SB_U32 (NFRAG * 32 * 4)      // 28672 u32 = 114688 B
#define RED_STRIDE 28                // floats per (wk,wm,lane) slot
#define SRED_FLOATS (3 * 128 * RED_STRIDE)
#define SMEM_RECUR (SB_U32 * 4 + SRED_FLOATS * 4)

__global__ __launch_bounds__(NTR, 1)
void recur_kernel(const float* __restrict__ W,
                  const float* __restrict__ dt,
                  const int* __restrict__ sl,
                  float* __restrict__ out_h,
                  float* __restrict__ out_final) {
    extern __shared__ uint32_t sB[];
    float* sRed = (float*)(sB + SB_U32);

    const int tid = threadIdx.x;
    const int w = tid >> 5;
    const int lane = tid & 31;
    const int g = lane >> 2;
    const int tq = lane & 3;
    const int wm = w & 3;            // m16 group (0..3)
    const int wk = w >> 2;           // k quarter (0..3)
    const int dn = blockIdx.x >> 1;
    const int bh = blockIdx.x & 1;
    const int d0 = dn * 8 + tq * 2;
    unsigned* barp = &g_bar2[bh * 32];

    // ---- pack W h-part fragments (interleaved hi/lo) ----
    for (int e = tid; e < NFRAG * 32; e += NTR) {
        int f = e >> 5;
        int l = e & 31;
        int ks = f / 7, nt = f % 7;
        int gg = l >> 2, tt = l & 3;
        int n = nt * Dh + dn * 8 + gg;
        const float* wr = W + (size_t)n * FIN + Iin + ks * 16;
        float w0 = wr[tt * 2], w1 = wr[tt * 2 + 1];
        float w2 = wr[tt * 2 + 8], w3 = wr[tt * 2 + 9];
        __nv_bfloat16 h0 = __float2bfloat16(w0), h1 = __float2bfloat16(w1);
        __nv_bfloat16 h2 = __float2bfloat16(w2), h3 = __float2bfloat16(w3);
        __nv_bfloat16 l0 = __float2bfloat16(w0 - __bfloat162float(h0));
        __nv_bfloat16 l1 = __float2bfloat16(w1 - __bfloat162float(h1));
        __nv_bfloat16 l2 = __float2bfloat16(w2 - __bfloat162float(h2));
        __nv_bfloat16 l3 = __float2bfloat16(w3 - __bfloat162float(h3));
        uint32_t* p = sB + (size_t)e * 4;
        p[0] = pack2bf(h0, h1);
        p[1] = pack2bf(h2, h3);
        p[2] = pack2bf(l0, l1);
        p[3] = pack2bf(l2, l3);
    }

    // rows: [rh] = bh*64 + wm*16 + rh*8 + g
    int rows[2];
    rows[0] = bh * 64 + wm * 16 + g;
    rows[1] = rows[0] + 8;

    int lenr[2] = {0, 0};
    float stC[2][2], stCe[2][2];

    if (wk == 0) {
        #pragma unroll
        for (int rh = 0; rh < 2; rh++) {
            int b = rows[rh];
            lenr[rh] = sl[b];
            float dtv = dt[b * Lseq + 0];
            float h2v[2];
            uint32_t hp[2];
            #pragma unroll
            for (int cj = 0; cj < 2; cj++) {
                int d = d0 + cj;
                float p0 = g_proj0[0 * Dh + d];
                float p2 = g_proj0[2 * Dh + d];
                float p4 = g_proj0[4 * Dh + d];
                float p5 = g_proj0[5 * Dh + d];
                float p6 = g_proj0[6 * Dh + d];
                float z   = tanhf(p5);
                float cs0 = sigf(p0) * z;
                float ce0 = sigf(p2) * z;
                float o0  = sigf(p4);
                float dn0 = softplusf(p6);
                float c = ce0 + (cs0 - ce0) * expf(-dn0 * dtv);
                float h = o0 * tanhf(c);
                stC[rh][cj] = c;
                stCe[rh][cj] = ce0;
                h2v[cj] = h;
                hp[cj] = pack_hl(h);
            }
            *(float2*)&out_h[((size_t)b * Lseq + 0) * Dh + d0] = make_float2(h2v[0], h2v[1]);
            *(uint2*)&g_Hsplit[0][b * Dh + d0] = make_uint2(hp[0], hp[1]);
        }
    }

    // acc: wk0 = XP2[0], others zero (XP2: contiguous per-block slice)
    float acc[7][4];
    if (wk == 0) {
        const float* xb = g_xp2 + (((size_t)0 * 64 + dn) * 128) * 56;
        #pragma unroll
        for (int nt = 0; nt < 7; nt++) {
            float2 x0 = *(const float2*)(xb + (size_t)rows[0] * 56 + nt * 8 + tq * 2);
            float2 x1 = *(const float2*)(xb + (size_t)rows[1] * 56 + nt * 8 + tq * 2);
            acc[nt][0] = x0.x; acc[nt][1] = x0.y;
            acc[nt][2] = x1.x; acc[nt][3] = x1.y;
        }
    } else {
        #pragma unroll
        for (int nt = 0; nt < 7; nt++)
            #pragma unroll
            for (int ci = 0; ci < 4; ci++) acc[nt][ci] = 0.0f;
    }

    __syncthreads();                         // sB + h0 stores ordered block-wide
    if (tid == 0) red_rel_add1(barp);        // 1 arrival/block -> 64/half

    unsigned tgt = 64;
    if (tid == 0) { while (ld_acq(barp) < tgt) {} }
    __syncthreads();

    const int kbase = wk * 128;              // u32 (d) offset of this k-quarter

    for (int t = 0; t < Lseq; t++) {
        const uint32_t* Hs = g_Hsplit[t & 1];

        // ring-2 A prefetch
        uint2 ring[2][4];
        #pragma unroll
        for (int p = 0; p < 2; p++) {
            int kb = kbase + p * 16 + tq * 2;
            ring[p][0] = *(const uint2*)(Hs + rows[0] * Dh + kb);
            ring[p][1] = *(const uint2*)(Hs + rows[1] * Dh + kb);
            ring[p][2] = *(const uint2*)(Hs + rows[0] * Dh + kb + 8);
            ring[p][3] = *(const uint2*)(Hs + rows[1] * Dh + kb + 8);
        }

        #pragma unroll 2
        for (int ks = 0; ks < 8; ks++) {
            int slot = ks & 1;
            uint32_t ah[4], al[4];
            #pragma unroll
            for (int q = 0; q < 4; q++) {
                ah[q] = prmt_(ring[slot][q].x, ring[slot][q].y, 0x5410);
                al[q] = prmt_(ring[slot][q].x, ring[slot][q].y, 0x7632);
            }
            if (ks + 2 < 8) {
                int kb = kbase + (ks + 2) * 16 + tq * 2;
                ring[slot][0] = *(const uint2*)(Hs + rows[0] * Dh + kb);
                ring[slot][1] = *(const uint2*)(Hs + rows[1] * Dh + kb);
                ring[slot][2] = *(const uint2*)(Hs + rows[0] * Dh + kb + 8);
                ring[slot][3] = *(const uint2*)(Hs + rows[1] * Dh + kb + 8);
            }
            int gks = wk * 8 + ks;
            uint4 bv[7];
            #pragma unroll
            for (int nt = 0; nt < 7; nt++)
                bv[nt] = *(const uint4*)(sB + (size_t)((gks * 7 + nt) * 32 + lane) * 4);
            // pass-outer: 7 independent accs between dependent MMAs
            #pragma unroll
            for (int nt = 0; nt < 7; nt++)
                MMA_BF16(acc[nt], ah, bv[nt].x, bv[nt].y);
            #pragma unroll
            for (int nt = 0; nt < 7; nt++)
                MMA_BF16(acc[nt], al, bv[nt].x, bv[nt].y);
            #pragma unroll
            for (int nt = 0; nt < 7; nt++)
                MMA_BF16(acc[nt], ah, bv[nt].z, bv[nt].w);
        }

        if (wk != 0) {
            float* rp = sRed + (size_t)(((wk - 1) * 128) + wm * 32 + lane) * RED_STRIDE;
            #pragma unroll
            for (int nt = 0; nt < 7; nt++)
                *(float4*)(rp + nt * 4) =
                    make_float4(acc[nt][0], acc[nt][1], acc[nt][2], acc[nt][3]);
            #pragma unroll
            for (int nt = 0; nt < 7; nt++)
                #pragma unroll
                for (int ci = 0; ci < 4; ci++) acc[nt][ci] = 0.0f;
        }
        __syncthreads();                     // sRed visible

        if (wk == 0) {
            #pragma unroll
            for (int q = 0; q < 3; q++) {
                const float4* rp = (const float4*)(sRed + (size_t)(q * 128 + wm * 32 + lane) * RED_STRIDE);
                #pragma unroll
                for (int nt = 0; nt < 7; nt++) {
                    float4 r = rp[nt];
                    acc[nt][0] += r.x; acc[nt][1] += r.y;
                    acc[nt][2] += r.z; acc[nt][3] += r.w;
                }
            }
            // ---- epilogue: gates + state for 2 rows x 2 d ----
            #pragma unroll
            for (int rh = 0; rh < 2; rh++) {
                int b = rows[rh];
                int len = lenr[rh];
                float dtv = 0.0f;
                if (t + 1 < Lseq) dtv = ((t + 1) < len) ? dt[b * Lseq + t + 1] : 0.0f;
                float hn[2];
                uint32_t hp[2];
                #pragma unroll
                for (int cj = 0; cj < 2; cj++) {
                    int ci = rh * 2 + cj;
                    float i_g  = sigf(acc[0][ci]);
                    float f_g  = sigf(acc[1][ci]);
                    float ie_g = sigf(acc[2][ci]);
                    float fe_g = sigf(acc[3][ci]);
                    float o_n  = sigf(acc[4][ci]);
                    float z    = tanhf(acc[5][ci]);
                    float d_n  = softplusf(acc[6][ci]);
                    float cs_n = f_g * stC[rh][cj] + i_g * z;
                    float ce_n = fe_g * stCe[rh][cj] + ie_g * z;
                    if (t == len - 1) {
                        float* f = out_final + (size_t)b * 4 * Dh + d0 + cj;
                        f[0 * Dh] = o_n;
                        f[1 * Dh] = cs_n;
                        f[2 * Dh] = ce_n;
                        f[3 * Dh] = d_n;
                    }
                    float cn = ce_n + (cs_n - ce_n) * expf(-d_n * dtv);
                    float h = o_n * tanhf(cn);
                    stC[rh][cj] = cn;
                    stCe[rh][cj] = ce_n;
                    hn[cj] = h;
                    hp[cj] = pack_hl(h);
                }
                if (t + 1 < Lseq) {
                    *(float2*)&out_h[((size_t)b * Lseq + (t + 1)) * Dh + d0] =
                        make_float2(hn[0], hn[1]);
                    *(uint2*)&g_Hsplit[(t + 1) & 1][b * Dh + d0] = make_uint2(hp[0], hp[1]);
                }
            }
            if (t + 1 < Lseq) {
                // prefetch XP2[t+1] into acc (contiguous; hidden behind barrier wait)
                const float* xb = g_xp2 + (((size_t)(t + 1) * 64 + dn) * 128) * 56;
                #pragma unroll
                for (int nt = 0; nt < 7; nt++) {
                    float2 x0 = *(const float2*)(xb + (size_t)rows[0] * 56 + nt * 8 + tq * 2);
                    float2 x1 = *(const float2*)(xb + (size_t)rows[1] * 56 + nt * 8 + tq * 2);
                    acc[nt][0] = x0.x; acc[nt][1] = x0.y;
                    acc[nt][2] = x1.x; acc[nt][3] = x1.y;
                }
                // wk0 warps sync (h publishes complete), then single arrival
                asm volatile("bar.sync 1, 128;" ::: "memory");
                if (tid == 0) red_rel_add1(barp);   // publish h_{t+1}, 1 arrival/block
            }
        }

        if (t + 1 < Lseq) {
            tgt += 64;
            if (tid == 0) { while (ld_acq(barp) < tgt) {} }
            __syncthreads();
        }
    }
}

// ---------------- launch ----------------
extern "C" void kernel_launch(void* const* d_in, const int* in_sizes, int n_in,
                              void* d_out, int out_size) {
    const float* x    = (const float*)d_in[0];   // (B,L,I)
    const float* dt   = (const float*)d_in[1];   // (B,L)
    const int*   sl   = (const int*)  d_in[2];   // (B,)
    const float* bos  = (const float*)d_in[3];   // (I,)
    const float* W    = (const float*)d_in[4];   // (7D, I+D)
    const float* bias = (const float*)d_in[5];   // (7D,)
    float* out = (float*)d_out;
    float* out_final = out + (size_t)Bsz * Lseq * Dh;

    cudaFuncSetAttribute(recur_kernel, cudaFuncAttributeMaxDynamicSharedMemorySize,
                         SMEM_RECUR);
    cudaFuncSetAttribute(xproj_hmma_kernel, cudaFuncAttributeMaxDynamicSharedMemorySize,
                         32768 * 4);

    prep_kernel<<<(ND + 255) / 256, 256>>>(bos, W, bias);
    pack_kernel<<<(XN + WN + 255) / 256, 256>>>(x, sl, W);
    xproj_hmma_kernel<<<dim3(28, 512), 256, 32768 * 4>>>(bias);
    recur_kernel<<<GRID_R, NTR, SMEM_RECUR>>>(W, dt, sl, out, out_final);
}

// round 11
// speedup vs baseline: 1.4680x; 1.1753x over previous
#include <cuda_runtime.h>
#include <cuda_fp16.h>
#include <math.h>
#include <stdint.h>

// Problem constants (ContTimeLSTM_66623532695635)
#define Bsz 128
#define Lseq 512
#define Iin 256
#define Dh 512
#define ND 3584          // 7*D
#define FIN 768          // I + D
#define BD (Bsz*Dh)      // 65536

#define GRID_R 128       // persistent recur blocks
#define NTR 512          // 16 warps: wm = w&3 (m16 group), wk = w>>2 (k quarter)

// ---------------- device scratch ----------------
// XP2 layout: [t][dn(64)][b(128)][gate(7)*8 + j]  -> per-block contiguous 14KB/step
__device__ float g_xp2[(size_t)Lseq * 64 * Bsz * 56];
__device__ uint32_t g_Hsplit[2][BD];                   // packed fp16 (hi | lo<<16)
__device__ uint32_t g_xpack[(size_t)Bsz * Lseq * Iin]; // packed masked x (fp16 hi|lo)
#define WFRAG_PLANE (28 * 16384)
__device__ uint32_t g_wfrag[WFRAG_PLANE];              // W x-part fragments (fp16 hi)
__device__ float g_proj0[ND];
__device__ __align__(256) unsigned g_bar2[64];         // [0]: half 0, [32]: half 1

__device__ __forceinline__ float sigf(float x) { return 1.0f / (1.0f + expf(-x)); }
__device__ __forceinline__ float softplusf(float x) {
    return (x > 0.0f) ? (x + log1pf(expf(-x))) : log1pf(expf(x));
}
__device__ __forceinline__ unsigned ld_acq(unsigned* p) {
    unsigned v;
    asm volatile("ld.acquire.gpu.u32 %0, [%1];" : "=r"(v) : "l"(p) : "memory");
    return v;
}
__device__ __forceinline__ void red_rel_add1(unsigned* p) {
    asm volatile("red.release.gpu.global.add.u32 [%0], 1;" :: "l"(p) : "memory");
}
__device__ __forceinline__ uint32_t prmt_(uint32_t a, uint32_t b, uint32_t s) {
    uint32_t r;
    asm("prmt.b32 %0, %1, %2, %3;" : "=r"(r) : "r"(a), "r"(b), "r"(s));
    return r;
}
// pack fp16 hi/lo split: u32 = (lo<<16) | hi
__device__ __forceinline__ uint32_t pack_hl(float v) {
    __half hi = __float2half_rn(v);
    __half lo = __float2half_rn(v - __half2float(hi));
    return ((uint32_t)__half_as_ushort(lo) << 16) | __half_as_ushort(hi);
}
__device__ __forceinline__ uint32_t pack2h(__half a, __half b) {
    return ((uint32_t)__half_as_ushort(b) << 16) | __half_as_ushort(a);
}

#define MMA_F16(d, a, b0, b1) \
    asm volatile("mma.sync.aligned.m16n8k16.row.col.f32.f16.f16.f32 " \
        "{%0,%1,%2,%3}, {%4,%5,%6,%7}, {%8,%9}, {%0,%1,%2,%3};" \
        : "+f"((d)[0]), "+f"((d)[1]), "+f"((d)[2]), "+f"((d)[3]) \
        : "r"((a)[0]), "r"((a)[1]), "r"((a)[2]), "r"((a)[3]), "r"(b0), "r"(b1))

// ---------------- launch 1: reset barriers + proj0 ----------------
__global__ void prep_kernel(const float* __restrict__ bos,
                            const float* __restrict__ W,
                            const float* __restrict__ bias) {
    int n = blockIdx.x * blockDim.x + threadIdx.x;
    if (n == 0) { g_bar2[0] = 0u; g_bar2[32] = 0u; }
    if (n >= ND) return;
    const float* wrow = W + (size_t)n * FIN;
    float acc = bias[n];
    #pragma unroll 8
    for (int i = 0; i < Iin; i++) acc += bos[i] * wrow[i];
    g_proj0[n] = acc;
}

// ---------------- launch 2: pack x (masked) + W x-part fragments ----------------
#define XN (Bsz * Lseq * Iin)          // 16,777,216
#define WN (28 * 16 * 16 * 32)         // 229,376
__global__ void pack_kernel(const float* __restrict__ x,
                            const int* __restrict__ sl,
                            const float* __restrict__ W) {
    int idx = blockIdx.x * blockDim.x + threadIdx.x;
    if (idx < XN) {
        int row = idx >> 8;
        int i = idx & 255;
        int t = row >> 7;
        int b = row & 127;
        float v = (t < __ldg(sl + b)) ? x[((size_t)b * Lseq + t) * Iin + i] : 0.0f;
        g_xpack[idx] = pack_hl(v);
        return;
    }
    int e = idx - XN;
    if (e >= WN) return;
    int lane = e & 31;
    int nt = (e >> 5) & 15;
    int ks = (e >> 9) & 15;
    int nb = e >> 13;
    int gg = lane >> 2, tt = lane & 3;
    int n = nb * 128 + nt * 8 + gg;
    const float* wr = W + (size_t)n * FIN + ks * 16 + tt * 2;
    __half h0 = __float2half_rn(wr[0]), h1 = __float2half_rn(wr[1]);
    __half h2 = __float2half_rn(wr[8]), h3 = __float2half_rn(wr[9]);
    size_t base = (size_t)e * 2;
    g_wfrag[base] = pack2h(h0, h1);
    g_wfrag[base + 1] = pack2h(h2, h3);
}

// ---------------- launch 3: XP = mask(x) @ Wx^T + bias via HMMA (fp16, 2-pass) ----------------
__global__ __launch_bounds__(256, 1)
void xproj_hmma_kernel(const float* __restrict__ bias) {
    extern __shared__ uint32_t sW[];   // 16384 u32 = 64 KB (single plane)
    const int tid = threadIdx.x;
    const int w = tid >> 5, lane = tid & 31;
    const int g = lane >> 2, tq = lane & 3;
    const int nb = blockIdx.x, mb = blockIdx.y;

    {
        const uint4* src = (const uint4*)(g_wfrag + (size_t)nb * 16384);
        uint4* dst = (uint4*)sW;
        #pragma unroll
        for (int i = 0; i < 16; i++) dst[tid + i * 256] = src[tid + i * 256];
    }
    __syncthreads();

    const int r0 = mb * 128 + w * 16 + g;

    float acc[16][4];
    #pragma unroll
    for (int nt = 0; nt < 16; nt++) {
        int n = nb * 128 + nt * 8 + tq * 2;
        float b0 = __ldg(bias + n), b1 = __ldg(bias + n + 1);
        acc[nt][0] = b0; acc[nt][1] = b1; acc[nt][2] = b0; acc[nt][3] = b1;
    }

    uint2 ring[2][4];
    #pragma unroll
    for (int p = 0; p < 2; p++) {
        int kb = p * 16 + tq * 2;
        ring[p][0] = *(const uint2*)(g_xpack + (size_t)r0 * Iin + kb);
        ring[p][1] = *(const uint2*)(g_xpack + (size_t)(r0 + 8) * Iin + kb);
        ring[p][2] = *(const uint2*)(g_xpack + (size_t)r0 * Iin + kb + 8);
        ring[p][3] = *(const uint2*)(g_xpack + (size_t)(r0 + 8) * Iin + kb + 8);
    }

    #pragma unroll 2
    for (int ks = 0; ks < 16; ks++) {
        int slot = ks & 1;
        uint32_t ah[4], al[4];
        #pragma unroll
        for (int q = 0; q < 4; q++) {
            ah[q] = prmt_(ring[slot][q].x, ring[slot][q].y, 0x5410);
            al[q] = prmt_(ring[slot][q].x, ring[slot][q].y, 0x7632);
        }
        if (ks + 2 < 16) {
            int kb = (ks + 2) * 16 + tq * 2;
            ring[slot][0] = *(const uint2*)(g_xpack + (size_t)r0 * Iin + kb);
            ring[slot][1] = *(const uint2*)(g_xpack + (size_t)(r0 + 8) * Iin + kb);
            ring[slot][2] = *(const uint2*)(g_xpack + (size_t)r0 * Iin + kb + 8);
            ring[slot][3] = *(const uint2*)(g_xpack + (size_t)(r0 + 8) * Iin + kb + 8);
        }
        uint32_t bhx[16][2];
        #pragma unroll
        for (int nt = 0; nt < 16; nt++) {
            uint2 vh = *(const uint2*)(sW + ((ks * 16 + nt) * 32 + lane) * 2);
            bhx[nt][0] = vh.x; bhx[nt][1] = vh.y;
            MMA_F16(acc[nt], ah, vh.x, vh.y);
        }
        #pragma unroll
        for (int nt = 0; nt < 16; nt++)
            MMA_F16(acc[nt], al, bhx[nt][0], bhx[nt][1]);
    }

    // epilogue: write into XP2 layout [t][dn][b][gate*8 + j]
    const int tt0 = r0 >> 7;
    const int b0 = r0 & 127;
    #pragma unroll
    for (int nt = 0; nt < 16; nt++) {
        int n = nb * 128 + nt * 8 + tq * 2;
        int gate = n >> 9;
        int dloc = n & 511;
        int dnx = dloc >> 3;
        size_t base = (((size_t)tt0 * 64 + dnx) * 128);
        size_t off = gate * 8 + (dloc & 7);
        *(float2*)&g_xp2[(base + b0) * 56 + off]     = make_float2(acc[nt][0], acc[nt][1]);
        *(float2*)&g_xp2[(base + b0 + 8) * 56 + off] = make_float2(acc[nt][2], acc[nt][3]);
    }
}

// ================= launch 4: persistent recurrence (fp16 2-pass) =================
// 128 blocks = 64 d-chunks x 2 batch-halves. 16 warps = 4 wm (m16) x 4 wk (K=128).
#define NFRAG 224                    // 32 ks * 7 nt
#define SB_U32 (NFRAG * 32 * 2)      // 14336 u32 = 57344 B (single fp16 plane)
#define RED_STRIDE 28                // floats per (wk,wm,lane) slot
#define SRED_FLOATS (3 * 128 * RED_STRIDE)
#define SMEM_RECUR (SB_U32 * 4 + SRED_FLOATS * 4)

__global__ __launch_bounds__(NTR, 1)
void recur_kernel(const float* __restrict__ W,
                  const float* __restrict__ dt,
                  const int* __restrict__ sl,
                  float* __restrict__ out_h,
                  float* __restrict__ out_final) {
    extern __shared__ uint32_t sB[];
    float* sRed = (float*)(sB + SB_U32);

    const int tid = threadIdx.x;
    const int w = tid >> 5;
    const int lane = tid & 31;
    const int g = lane >> 2;
    const int tq = lane & 3;
    const int wm = w & 3;            // m16 group (0..3)
    const int wk = w >> 2;           // k quarter (0..3)
    const int dn = blockIdx.x >> 1;
    const int bh = blockIdx.x & 1;
    const int d0 = dn * 8 + tq * 2;
    unsigned* barp = &g_bar2[bh * 32];

    // ---- pack W h-part fragments (fp16 hi only) ----
    for (int e = tid; e < NFRAG * 32; e += NTR) {
        int f = e >> 5;
        int l = e & 31;
        int ks = f / 7, nt = f % 7;
        int gg = l >> 2, tt = l & 3;
        int n = nt * Dh + dn * 8 + gg;
        const float* wr = W + (size_t)n * FIN + Iin + ks * 16;
        __half h0 = __float2half_rn(wr[tt * 2]),     h1 = __float2half_rn(wr[tt * 2 + 1]);
        __half h2 = __float2half_rn(wr[tt * 2 + 8]), h3 = __float2half_rn(wr[tt * 2 + 9]);
        uint32_t* p = sB + (size_t)e * 2;
        p[0] = pack2h(h0, h1);
        p[1] = pack2h(h2, h3);
    }

    // rows: [rh] = bh*64 + wm*16 + rh*8 + g
    int rows[2];
    rows[0] = bh * 64 + wm * 16 + g;
    rows[1] = rows[0] + 8;

    int lenr[2] = {0, 0};
    float stC[2][2], stCe[2][2];

    if (wk == 0) {
        #pragma unroll
        for (int rh = 0; rh < 2; rh++) {
            int b = rows[rh];
            lenr[rh] = sl[b];
            float dtv = dt[b * Lseq + 0];
            float h2v[2];
            uint32_t hp[2];
            #pragma unroll
            for (int cj = 0; cj < 2; cj++) {
                int d = d0 + cj;
                float p0 = g_proj0[0 * Dh + d];
                float p2 = g_proj0[2 * Dh + d];
                float p4 = g_proj0[4 * Dh + d];
                float p5 = g_proj0[5 * Dh + d];
                float p6 = g_proj0[6 * Dh + d];
                float z   = tanhf(p5);
                float cs0 = sigf(p0) * z;
                float ce0 = sigf(p2) * z;
                float o0  = sigf(p4);
                float dn0 = softplusf(p6);
                float c = ce0 + (cs0 - ce0) * expf(-dn0 * dtv);
                float h = o0 * tanhf(c);
                stC[rh][cj] = c;
                stCe[rh][cj] = ce0;
                h2v[cj] = h;
                hp[cj] = pack_hl(h);
            }
            *(float2*)&out_h[((size_t)b * Lseq + 0) * Dh + d0] = make_float2(h2v[0], h2v[1]);
            *(uint2*)&g_Hsplit[0][b * Dh + d0] = make_uint2(hp[0], hp[1]);
        }
    }

    // acc: wk0 = XP2[0], others zero
    float acc[7][4];
    if (wk == 0) {
        const float* xb = g_xp2 + (((size_t)0 * 64 + dn) * 128) * 56;
        #pragma unroll
        for (int nt = 0; nt < 7; nt++) {
            float2 x0 = *(const float2*)(xb + (size_t)rows[0] * 56 + nt * 8 + tq * 2);
            float2 x1 = *(const float2*)(xb + (size_t)rows[1] * 56 + nt * 8 + tq * 2);
            acc[nt][0] = x0.x; acc[nt][1] = x0.y;
            acc[nt][2] = x1.x; acc[nt][3] = x1.y;
        }
    } else {
        #pragma unroll
        for (int nt = 0; nt < 7; nt++)
            #pragma unroll
            for (int ci = 0; ci < 4; ci++) acc[nt][ci] = 0.0f;
    }

    __syncthreads();                         // sB + h0 stores ordered block-wide
    if (tid == 0) red_rel_add1(barp);        // 1 arrival/block -> 64/half

    unsigned tgt = 64;
    if (tid == 0) { while (ld_acq(barp) < tgt) {} }
    __syncthreads();

    const int kbase = wk * 128;              // u32 (d) offset of this k-quarter

    for (int t = 0; t < Lseq; t++) {
        const uint32_t* Hs = g_Hsplit[t & 1];

        // ring-2 A prefetch
        uint2 ring[2][4];
        #pragma unroll
        for (int p = 0; p < 2; p++) {
            int kb = kbase + p * 16 + tq * 2;
            ring[p][0] = *(const uint2*)(Hs + rows[0] * Dh + kb);
            ring[p][1] = *(const uint2*)(Hs + rows[1] * Dh + kb);
            ring[p][2] = *(const uint2*)(Hs + rows[0] * Dh + kb + 8);
            ring[p][3] = *(const uint2*)(Hs + rows[1] * Dh + kb + 8);
        }

        #pragma unroll 2
        for (int ks = 0; ks < 8; ks++) {
            int slot = ks & 1;
            uint32_t ah[4], al[4];
            #pragma unroll
            for (int q = 0; q < 4; q++) {
                ah[q] = prmt_(ring[slot][q].x, ring[slot][q].y, 0x5410);
                al[q] = prmt_(ring[slot][q].x, ring[slot][q].y, 0x7632);
            }
            if (ks + 2 < 8) {
                int kb = kbase + (ks + 2) * 16 + tq * 2;
                ring[slot][0] = *(const uint2*)(Hs + rows[0] * Dh + kb);
                ring[slot][1] = *(const uint2*)(Hs + rows[1] * Dh + kb);
                ring[slot][2] = *(const uint2*)(Hs + rows[0] * Dh + kb + 8);
                ring[slot][3] = *(const uint2*)(Hs + rows[1] * Dh + kb + 8);
            }
            int gks = wk * 8 + ks;
            uint2 bv[7];
            #pragma unroll
            for (int nt = 0; nt < 7; nt++)
                bv[nt] = *(const uint2*)(sB + (size_t)((gks * 7 + nt) * 32 + lane) * 2);
            // 2-pass: hi then lo, pass-outer (7 independent accs)
            #pragma unroll
            for (int nt = 0; nt < 7; nt++)
                MMA_F16(acc[nt], ah, bv[nt].x, bv[nt].y);
            #pragma unroll
            for (int nt = 0; nt < 7; nt++)
                MMA_F16(acc[nt], al, bv[nt].x, bv[nt].y);
        }

        if (wk != 0) {
            float* rp = sRed + (size_t)(((wk - 1) * 128) + wm * 32 + lane) * RED_STRIDE;
            #pragma unroll
            for (int nt = 0; nt < 7; nt++)
                *(float4*)(rp + nt * 4) =
                    make_float4(acc[nt][0], acc[nt][1], acc[nt][2], acc[nt][3]);
            #pragma unroll
            for (int nt = 0; nt < 7; nt++)
                #pragma unroll
                for (int ci = 0; ci < 4; ci++) acc[nt][ci] = 0.0f;
        }
        __syncthreads();                     // sRed visible

        if (wk == 0) {
            #pragma unroll
            for (int q = 0; q < 3; q++) {
                const float4* rp = (const float4*)(sRed + (size_t)(q * 128 + wm * 32 + lane) * RED_STRIDE);
                #pragma unroll
                for (int nt = 0; nt < 7; nt++) {
                    float4 r = rp[nt];
                    acc[nt][0] += r.x; acc[nt][1] += r.y;
                    acc[nt][2] += r.z; acc[nt][3] += r.w;
                }
            }
            // ---- epilogue: gates + state for 2 rows x 2 d ----
            #pragma unroll
            for (int rh = 0; rh < 2; rh++) {
                int b = rows[rh];
                int len = lenr[rh];
                float dtv = 0.0f;
                if (t + 1 < Lseq) dtv = ((t + 1) < len) ? dt[b * Lseq + t + 1] : 0.0f;
                float hn[2];
                uint32_t hp[2];
                #pragma unroll
                for (int cj = 0; cj < 2; cj++) {
                    int ci = rh * 2 + cj;
                    float i_g  = sigf(acc[0][ci]);
                    float f_g  = sigf(acc[1][ci]);
                    float ie_g = sigf(acc[2][ci]);
                    float fe_g = sigf(acc[3][ci]);
                    float o_n  = sigf(acc[4][ci]);
                    float z    = tanhf(acc[5][ci]);
                    float d_n  = softplusf(acc[6][ci]);
                    float cs_n = f_g * stC[rh][cj] + i_g * z;
                    float ce_n = fe_g * stCe[rh][cj] + ie_g * z;
                    if (t == len - 1) {
                        float* f = out_final + (size_t)b * 4 * Dh + d0 + cj;
                        f[0 * Dh] = o_n;
                        f[1 * Dh] = cs_n;
                        f[2 * Dh] = ce_n;
                        f[3 * Dh] = d_n;
                    }
                    float cn = ce_n + (cs_n - ce_n) * expf(-d_n * dtv);
                    float h = o_n * tanhf(cn);
                    stC[rh][cj] = cn;
                    stCe[rh][cj] = ce_n;
                    hn[cj] = h;
                    hp[cj] = pack_hl(h);
                }
                if (t + 1 < Lseq) {
                    *(float2*)&out_h[((size_t)b * Lseq + (t + 1)) * Dh + d0] =
                        make_float2(hn[0], hn[1]);
                    *(uint2*)&g_Hsplit[(t + 1) & 1][b * Dh + d0] = make_uint2(hp[0], hp[1]);
                }
            }
            if (t + 1 < Lseq) {
                // prefetch XP2[t+1] into acc (contiguous; hidden behind barrier wait)
                const float* xb = g_xp2 + (((size_t)(t + 1) * 64 + dn) * 128) * 56;
                #pragma unroll
                for (int nt = 0; nt < 7; nt++) {
                    float2 x0 = *(const float2*)(xb + (size_t)rows[0] * 56 + nt * 8 + tq * 2);
                    float2 x1 = *(const float2*)(xb + (size_t)rows[1] * 56 + nt * 8 + tq * 2);
                    acc[nt][0] = x0.x; acc[nt][1] = x0.y;
                    acc[nt][2] = x1.x; acc[nt][3] = x1.y;
                }
                // wk0 warps sync (h publishes complete), then single arrival
                asm volatile("bar.sync 1, 128;" ::: "memory");
                if (tid == 0) red_rel_add1(barp);   // publish h_{t+1}, 1 arrival/block
            }
        }

        if (t + 1 < Lseq) {
            tgt += 64;
            if (tid == 0) { while (ld_acq(barp) < tgt) {} }
            __syncthreads();
        }
    }
}

// ---------------- launch ----------------
extern "C" void kernel_launch(void* const* d_in, const int* in_sizes, int n_in,
                              void* d_out, int out_size) {
    const float* x    = (const float*)d_in[0];   // (B,L,I)
    const float* dt   = (const float*)d_in[1];   // (B,L)
    const int*   sl   = (const int*)  d_in[2];   // (B,)
    const float* bos  = (const float*)d_in[3];   // (I,)
    const float* W    = (const float*)d_in[4];   // (7D, I+D)
    const float* bias = (const float*)d_in[5];   // (7D,)
    float* out = (float*)d_out;
    float* out_final = out + (size_t)Bsz * Lseq * Dh;

    cudaFuncSetAttribute(recur_kernel, cudaFuncAttributeMaxDynamicSharedMemorySize,
                         SMEM_RECUR);
    cudaFuncSetAttribute(xproj_hmma_kernel, cudaFuncAttributeMaxDynamicSharedMemorySize,
                         16384 * 4);

    prep_kernel<<<(ND + 255) / 256, 256>>>(bos, W, bias);
    pack_kernel<<<(XN + WN + 255) / 256, 256>>>(x, sl, W);
    xproj_hmma_kernel<<<dim3(28, 512), 256, 16384 * 4>>>(bias);
    recur_kernel<<<GRID_R, NTR, SMEM_RECUR>>>(W, dt, sl, out, out_final);
}

// round 13
// speedup vs baseline: 1.6443x; 1.1201x over previous
#include <cuda_runtime.h>
#include <cuda_fp16.h>
#include <math.h>
#include <stdint.h>

// Problem constants (ContTimeLSTM_66623532695635)
#define Bsz 128
#define Lseq 512
#define Iin 256
#define Dh 512
#define ND 3584          // 7*D
#define FIN 768          // I + D
#define BD (Bsz*Dh)      // 65536

#define GRID_R 128       // persistent recur blocks
#define NTR 512          // 16 warps: wm = w&3 (m16 group), wk = w>>2 (k quarter)

// ---------------- device scratch ----------------
// XP2 layout: [t][dn(64)][b(128)][gate(7)*8 + j]
__device__ float g_xp2[(size_t)Lseq * 64 * Bsz * 56];
__device__ uint32_t g_Hsplit[2][BD];                   // packed fp16 (hi | lo<<16)
__device__ uint32_t g_xpack[(size_t)Bsz * Lseq * Iin]; // packed masked x (fp16 hi|lo)
#define WFRAG_PLANE (28 * 16384)
__device__ uint32_t g_wfrag[WFRAG_PLANE];              // W x-part fragments (fp16)
__device__ float g_proj0[ND];
__device__ __align__(256) unsigned g_bar2[64];         // [0]: half 0, [32]: half 1

// ---- fast transcendentals (MUFU-based; rel err ~2^-21, negligible vs 2e-4) ----
__device__ __forceinline__ float sigf(float x) {
    return __fdividef(1.0f, 1.0f + __expf(-x));
}
__device__ __forceinline__ float tanhf_fast(float x) {
    float xc = fminf(fmaxf(x, -15.0f), 15.0f);
    float e = __expf(2.0f * xc);
    return __fdividef(e - 1.0f, e + 1.0f);
}
__device__ __forceinline__ float softplusf(float x) {
    if (x > 0.0f) return x + __logf(1.0f + __expf(-x));
    return __logf(1.0f + __expf(x));
}
__device__ __forceinline__ unsigned ld_acq(unsigned* p) {
    unsigned v;
    asm volatile("ld.acquire.gpu.u32 %0, [%1];" : "=r"(v) : "l"(p) : "memory");
    return v;
}
__device__ __forceinline__ void red_rel_add1(unsigned* p) {
    asm volatile("red.release.gpu.global.add.u32 [%0], 1;" :: "l"(p) : "memory");
}
__device__ __forceinline__ uint32_t prmt_(uint32_t a, uint32_t b, uint32_t s) {
    uint32_t r;
    asm("prmt.b32 %0, %1, %2, %3;" : "=r"(r) : "r"(a), "r"(b), "r"(s));
    return r;
}
__device__ __forceinline__ uint32_t pack_hl(float v) {
    __half hi = __float2half_rn(v);
    __half lo = __float2half_rn(v - __half2float(hi));
    return ((uint32_t)__half_as_ushort(lo) << 16) | __half_as_ushort(hi);
}
__device__ __forceinline__ uint32_t pack2h(__half a, __half b) {
    return ((uint32_t)__half_as_ushort(b) << 16) | __half_as_ushort(a);
}

#define MMA_F16(d, a, b0, b1) \
    asm volatile("mma.sync.aligned.m16n8k16.row.col.f32.f16.f16.f32 " \
        "{%0,%1,%2,%3}, {%4,%5,%6,%7}, {%8,%9}, {%0,%1,%2,%3};" \
        : "+f"((d)[0]), "+f"((d)[1]), "+f"((d)[2]), "+f"((d)[3]) \
        : "r"((a)[0]), "r"((a)[1]), "r"((a)[2]), "r"((a)[3]), "r"(b0), "r"(b1))

// ---------------- launch 1: reset barriers + proj0 ----------------
__global__ void prep_kernel(const float* __restrict__ bos,
                            const float* __restrict__ W,
                            const float* __restrict__ bias) {
    int n = blockIdx.x * blockDim.x + threadIdx.x;
    if (n == 0) { g_bar2[0] = 0u; g_bar2[32] = 0u; }
    if (n >= ND) return;
    const float* wrow = W + (size_t)n * FIN;
    float acc = bias[n];
    #pragma unroll 8
    for (int i = 0; i < Iin; i++) acc += bos[i] * wrow[i];
    g_proj0[n] = acc;
}

// ---------------- launch 2: pack x (masked) + W x-part fragments ----------------
#define XN (Bsz * Lseq * Iin)          // 16,777,216
#define WN (28 * 16 * 16 * 32)         // 229,376
__global__ void pack_kernel(const float* __restrict__ x,
                            const int* __restrict__ sl,
                            const float* __restrict__ W) {
    int idx = blockIdx.x * blockDim.x + threadIdx.x;
    if (idx < XN) {
        int row = idx >> 8;
        int i = idx & 255;
        int t = row >> 7;
        int b = row & 127;
        float v = (t < __ldg(sl + b)) ? x[((size_t)b * Lseq + t) * Iin + i] : 0.0f;
        g_xpack[idx] = pack_hl(v);
        return;
    }
    int e = idx - XN;
    if (e >= WN) return;
    int lane = e & 31;
    int nt = (e >> 5) & 15;
    int ks = (e >> 9) & 15;
    int nb = e >> 13;
    int gg = lane >> 2, tt = lane & 3;
    int n = nb * 128 + nt * 8 + gg;
    const float* wr = W + (size_t)n * FIN + ks * 16 + tt * 2;
    __half h0 = __float2half_rn(wr[0]), h1 = __float2half_rn(wr[1]);
    __half h2 = __float2half_rn(wr[8]), h3 = __float2half_rn(wr[9]);
    size_t base = (size_t)e * 2;
    g_wfrag[base] = pack2h(h0, h1);
    g_wfrag[base + 1] = pack2h(h2, h3);
}

// ---------------- launch 3: XP = mask(x) @ Wx^T + bias via HMMA (fp16, 2-pass) ----------------
__global__ __launch_bounds__(256, 1)
void xproj_hmma_kernel(const float* __restrict__ bias) {
    extern __shared__ uint32_t sW[];   // 16384 u32 = 64 KB
    const int tid = threadIdx.x;
    const int w = tid >> 5, lane = tid & 31;
    const int g = lane >> 2, tq = lane & 3;
    const int nb = blockIdx.x, mb = blockIdx.y;

    {
        const uint4* src = (const uint4*)(g_wfrag + (size_t)nb * 16384);
        uint4* dst = (uint4*)sW;
        #pragma unroll
        for (int i = 0; i < 16; i++) dst[tid + i * 256] = src[tid + i * 256];
    }
    __syncthreads();

    const int r0 = mb * 128 + w * 16 + g;

    float acc[16][4];
    #pragma unroll
    for (int nt = 0; nt < 16; nt++) {
        int n = nb * 128 + nt * 8 + tq * 2;
        float b0 = __ldg(bias + n), b1 = __ldg(bias + n + 1);
        acc[nt][0] = b0; acc[nt][1] = b1; acc[nt][2] = b0; acc[nt][3] = b1;
    }

    uint2 ring[2][4];
    #pragma unroll
    for (int p = 0; p < 2; p++) {
        int kb = p * 16 + tq * 2;
        ring[p][0] = *(const uint2*)(g_xpack + (size_t)r0 * Iin + kb);
        ring[p][1] = *(const uint2*)(g_xpack + (size_t)(r0 + 8) * Iin + kb);
        ring[p][2] = *(const uint2*)(g_xpack + (size_t)r0 * Iin + kb + 8);
        ring[p][3] = *(const uint2*)(g_xpack + (size_t)(r0 + 8) * Iin + kb + 8);
    }

    #pragma unroll 2
    for (int ks = 0; ks < 16; ks++) {
        int slot = ks & 1;
        uint32_t ah[4], al[4];
        #pragma unroll
        for (int q = 0; q < 4; q++) {
            ah[q] = prmt_(ring[slot][q].x, ring[slot][q].y, 0x5410);
            al[q] = prmt_(ring[slot][q].x, ring[slot][q].y, 0x7632);
        }
        if (ks + 2 < 16) {
            int kb = (ks + 2) * 16 + tq * 2;
            ring[slot][0] = *(const uint2*)(g_xpack + (size_t)r0 * Iin + kb);
            ring[slot][1] = *(const uint2*)(g_xpack + (size_t)(r0 + 8) * Iin + kb);
            ring[slot][2] = *(const uint2*)(g_xpack + (size_t)r0 * Iin + kb + 8);
            ring[slot][3] = *(const uint2*)(g_xpack + (size_t)(r0 + 8) * Iin + kb + 8);
        }
        uint32_t bhx[16][2];
        #pragma unroll
        for (int nt = 0; nt < 16; nt++) {
            uint2 vh = *(const uint2*)(sW + ((ks * 16 + nt) * 32 + lane) * 2);
            bhx[nt][0] = vh.x; bhx[nt][1] = vh.y;
            MMA_F16(acc[nt], ah, vh.x, vh.y);
        }
        #pragma unroll
        for (int nt = 0; nt < 16; nt++)
            MMA_F16(acc[nt], al, bhx[nt][0], bhx[nt][1]);
    }

    // epilogue: write into XP2 layout [t][dn][b][gate*8 + j]
    const int tt0 = r0 >> 7;
    const int b0 = r0 & 127;
    #pragma unroll
    for (int nt = 0; nt < 16; nt++) {
        int n = nb * 128 + nt * 8 + tq * 2;
        int gate = n >> 9;
        int dloc = n & 511;
        int dnx = dloc >> 3;
        size_t base = (((size_t)tt0 * 64 + dnx) * 128);
        size_t off = gate * 8 + (dloc & 7);
        *(float2*)&g_xp2[(base + b0) * 56 + off]     = make_float2(acc[nt][0], acc[nt][1]);
        *(float2*)&g_xp2[(base + b0 + 8) * 56 + off] = make_float2(acc[nt][2], acc[nt][3]);
    }
}

// ================= launch 4: persistent recurrence (fp16 2-pass) =================
#define NFRAG 224                    // 32 ks * 7 nt
#define SB_U32 (NFRAG * 32 * 2)      // 14336 u32 = 57344 B (single fp16 plane)
#define RED_STRIDE 29                // odd stride -> conflict-free; SCALAR access only
#define SRED_FLOATS (3 * 128 * RED_STRIDE)
#define SMEM_RECUR (SB_U32 * 4 + SRED_FLOATS * 4)

__global__ __launch_bounds__(NTR, 1)
void recur_kernel(const float* __restrict__ W,
                  const float* __restrict__ dt,
                  const int* __restrict__ sl,
                  float* __restrict__ out_h,
                  float* __restrict__ out_final) {
    extern __shared__ uint32_t sB[];
    float* sRed = (float*)(sB + SB_U32);

    const int tid = threadIdx.x;
    const int w = tid >> 5;
    const int lane = tid & 31;
    const int g = lane >> 2;
    const int tq = lane & 3;
    const int wm = w & 3;            // m16 group (0..3)
    const int wk = w >> 2;           // k quarter (0..3)
    const int dn = blockIdx.x >> 1;
    const int bh = blockIdx.x & 1;
    const int d0 = dn * 8 + tq * 2;
    unsigned* barp = &g_bar2[bh * 32];

    // ---- pack W h-part fragments (fp16) ----
    for (int e = tid; e < NFRAG * 32; e += NTR) {
        int f = e >> 5;
        int l = e & 31;
        int ks = f / 7, nt = f % 7;
        int gg = l >> 2, tt = l & 3;
        int n = nt * Dh + dn * 8 + gg;
        const float* wr = W + (size_t)n * FIN + Iin + ks * 16;
        __half h0 = __float2half_rn(wr[tt * 2]),     h1 = __float2half_rn(wr[tt * 2 + 1]);
        __half h2 = __float2half_rn(wr[tt * 2 + 8]), h3 = __float2half_rn(wr[tt * 2 + 9]);
        uint32_t* p = sB + (size_t)e * 2;
        p[0] = pack2h(h0, h1);
        p[1] = pack2h(h2, h3);
    }

    int rows[2];
    rows[0] = bh * 64 + wm * 16 + g;
    rows[1] = rows[0] + 8;

    int lenr[2] = {0, 0};
    float stC[2][2], stCe[2][2];

    if (wk == 0) {
        #pragma unroll
        for (int rh = 0; rh < 2; rh++) {
            int b = rows[rh];
            lenr[rh] = sl[b];
            float dtv = dt[b * Lseq + 0];
            float h2v[2];
            uint32_t hp[2];
            #pragma unroll
            for (int cj = 0; cj < 2; cj++) {
                int d = d0 + cj;
                float p0 = g_proj0[0 * Dh + d];
                float p2 = g_proj0[2 * Dh + d];
                float p4 = g_proj0[4 * Dh + d];
                float p5 = g_proj0[5 * Dh + d];
                float p6 = g_proj0[6 * Dh + d];
                float z   = tanhf_fast(p5);
                float cs0 = sigf(p0) * z;
                float ce0 = sigf(p2) * z;
                float o0  = sigf(p4);
                float dn0 = softplusf(p6);
                float c = ce0 + (cs0 - ce0) * __expf(-dn0 * dtv);
                float h = o0 * tanhf_fast(c);
                stC[rh][cj] = c;
                stCe[rh][cj] = ce0;
                h2v[cj] = h;
                hp[cj] = pack_hl(h);
            }
            *(float2*)&out_h[((size_t)b * Lseq + 0) * Dh + d0] = make_float2(h2v[0], h2v[1]);
            *(uint2*)&g_Hsplit[0][b * Dh + d0] = make_uint2(hp[0], hp[1]);
        }
    }

    // acc: wk0 = XP2[0], others zero
    float acc[7][4];
    if (wk == 0) {
        const float* xb = g_xp2 + (((size_t)0 * 64 + dn) * 128) * 56;
        #pragma unroll
        for (int nt = 0; nt < 7; nt++) {
            float2 x0 = *(const float2*)(xb + (size_t)rows[0] * 56 + nt * 8 + tq * 2);
            float2 x1 = *(const float2*)(xb + (size_t)rows[1] * 56 + nt * 8 + tq * 2);
            acc[nt][0] = x0.x; acc[nt][1] = x0.y;
            acc[nt][2] = x1.x; acc[nt][3] = x1.y;
        }
    } else {
        #pragma unroll
        for (int nt = 0; nt < 7; nt++)
            #pragma unroll
            for (int ci = 0; ci < 4; ci++) acc[nt][ci] = 0.0f;
    }

    __syncthreads();                         // sB + h0 stores ordered block-wide
    if (tid == 0) red_rel_add1(barp);        // 1 arrival/block -> 64/half

    unsigned tgt = 64;
    if (tid == 0) { while (ld_acq(barp) < tgt) {} }
    __syncthreads();

    const int kbase = wk * 128;

    for (int t = 0; t < Lseq; t++) {
        const uint32_t* Hs = g_Hsplit[t & 1];

        // ring-2 A prefetch
        uint2 ring[2][4];
        #pragma unroll
        for (int p = 0; p < 2; p++) {
            int kb = kbase + p * 16 + tq * 2;
            ring[p][0] = *(const uint2*)(Hs + rows[0] * Dh + kb);
            ring[p][1] = *(const uint2*)(Hs + rows[1] * Dh + kb);
            ring[p][2] = *(const uint2*)(Hs + rows[0] * Dh + kb + 8);
            ring[p][3] = *(const uint2*)(Hs + rows[1] * Dh + kb + 8);
        }

        #pragma unroll 2
        for (int ks = 0; ks < 8; ks++) {
            int slot = ks & 1;
            uint32_t ah[4], al[4];
            #pragma unroll
            for (int q = 0; q < 4; q++) {
                ah[q] = prmt_(ring[slot][q].x, ring[slot][q].y, 0x5410);
                al[q] = prmt_(ring[slot][q].x, ring[slot][q].y, 0x7632);
            }
            if (ks + 2 < 8) {
                int kb = kbase + (ks + 2) * 16 + tq * 2;
                ring[slot][0] = *(const uint2*)(Hs + rows[0] * Dh + kb);
                ring[slot][1] = *(const uint2*)(Hs + rows[1] * Dh + kb);
                ring[slot][2] = *(const uint2*)(Hs + rows[0] * Dh + kb + 8);
                ring[slot][3] = *(const uint2*)(Hs + rows[1] * Dh + kb + 8);
            }
            int gks = wk * 8 + ks;
            uint2 bv[7];
            #pragma unroll
            for (int nt = 0; nt < 7; nt++)
                bv[nt] = *(const uint2*)(sB + (size_t)((gks * 7 + nt) * 32 + lane) * 2);
            #pragma unroll
            for (int nt = 0; nt < 7; nt++)
                MMA_F16(acc[nt], ah, bv[nt].x, bv[nt].y);
            #pragma unroll
            for (int nt = 0; nt < 7; nt++)
                MMA_F16(acc[nt], al, bv[nt].x, bv[nt].y);
        }

        if (wk != 0) {
            // scalar stores, odd stride -> conflict-free, 4B-aligned
            float* rp = sRed + (size_t)(((wk - 1) * 128) + wm * 32 + lane) * RED_STRIDE;
            #pragma unroll
            for (int nt = 0; nt < 7; nt++) {
                rp[nt * 4 + 0] = acc[nt][0];
                rp[nt * 4 + 1] = acc[nt][1];
                rp[nt * 4 + 2] = acc[nt][2];
                rp[nt * 4 + 3] = acc[nt][3];
            }
            #pragma unroll
            for (int nt = 0; nt < 7; nt++)
                #pragma unroll
                for (int ci = 0; ci < 4; ci++) acc[nt][ci] = 0.0f;
        }
        __syncthreads();                     // sRed visible

        if (wk == 0) {
            #pragma unroll
            for (int q = 0; q < 3; q++) {
                const float* rp = sRed + (size_t)(q * 128 + wm * 32 + lane) * RED_STRIDE;
                #pragma unroll
                for (int nt = 0; nt < 7; nt++) {
                    acc[nt][0] += rp[nt * 4 + 0];
                    acc[nt][1] += rp[nt * 4 + 1];
                    acc[nt][2] += rp[nt * 4 + 2];
                    acc[nt][3] += rp[nt * 4 + 3];
                }
            }
            // ---- epilogue: gates + state for 2 rows x 2 d ----
            #pragma unroll
            for (int rh = 0; rh < 2; rh++) {
                int b = rows[rh];
                int len = lenr[rh];
                float dtv = 0.0f;
                if (t + 1 < Lseq) dtv = ((t + 1) < len) ? dt[b * Lseq + t + 1] : 0.0f;
                float hn[2];
                uint32_t hp[2];
                #pragma unroll
                for (int cj = 0; cj < 2; cj++) {
                    int ci = rh * 2 + cj;
                    float i_g  = sigf(acc[0][ci]);
                    float f_g  = sigf(acc[1][ci]);
                    float ie_g = sigf(acc[2][ci]);
                    float fe_g = sigf(acc[3][ci]);
                    float o_n  = sigf(acc[4][ci]);
                    float z    = tanhf_fast(acc[5][ci]);
                    float d_n  = softplusf(acc[6][ci]);
                    float cs_n = f_g * stC[rh][cj] + i_g * z;
                    float ce_n = fe_g * stCe[rh][cj] + ie_g * z;
                    if (t == len - 1) {
                        float* f = out_final + (size_t)b * 4 * Dh + d0 + cj;
                        f[0 * Dh] = o_n;
                        f[1 * Dh] = cs_n;
                        f[2 * Dh] = ce_n;
                        f[3 * Dh] = d_n;
                    }
                    float cn = ce_n + (cs_n - ce_n) * __expf(-d_n * dtv);
                    float h = o_n * tanhf_fast(cn);
                    stC[rh][cj] = cn;
                    stCe[rh][cj] = ce_n;
                    hn[cj] = h;
                    hp[cj] = pack_hl(h);
                }
                if (t + 1 < Lseq) {
                    *(float2*)&out_h[((size_t)b * Lseq + (t + 1)) * Dh + d0] =
                        make_float2(hn[0], hn[1]);
                    *(uint2*)&g_Hsplit[(t + 1) & 1][b * Dh + d0] = make_uint2(hp[0], hp[1]);
                }
            }
            if (t + 1 < Lseq) {
                // prefetch XP2[t+1] into acc (contiguous; hidden behind barrier wait)
                const float* xb = g_xp2 + (((size_t)(t + 1) * 64 + dn) * 128) * 56;
                #pragma unroll
                for (int nt = 0; nt < 7; nt++) {
                    float2 x0 = *(const float2*)(xb + (size_t)rows[0] * 56 + nt * 8 + tq * 2);
                    float2 x1 = *(const float2*)(xb + (size_t)rows[1] * 56 + nt * 8 + tq * 2);
                    acc[nt][0] = x0.x; acc[nt][1] = x0.y;
                    acc[nt][2] = x1.x; acc[nt][3] = x1.y;
                }
                asm volatile("bar.sync 1, 128;" ::: "memory");
                if (tid == 0) red_rel_add1(barp);   // publish h_{t+1}
            }
        }

        if (t + 1 < Lseq) {
            tgt += 64;
            if (tid == 0) { while (ld_acq(barp) < tgt) {} }
            __syncthreads();
        }
    }
}

// ---------------- launch ----------------
extern "C" void kernel_launch(void* const* d_in, const int* in_sizes, int n_in,
                              void* d_out, int out_size) {
    const float* x    = (const float*)d_in[0];   // (B,L,I)
    const float* dt   = (const float*)d_in[1];   // (B,L)
    const int*   sl   = (const int*)  d_in[2];   // (B,)
    const float* bos  = (const float*)d_in[3];   // (I,)
    const float* W    = (const float*)d_in[4];   // (7D, I+D)
    const float* bias = (const float*)d_in[5];   // (7D,)
    float* out = (float*)d_out;
    float* out_final = out + (size_t)Bsz * Lseq * Dh;

    cudaFuncSetAttribute(recur_kernel, cudaFuncAttributeMaxDynamicSharedMemorySize,
                         SMEM_RECUR);
    cudaFuncSetAttribute(xproj_hmma_kernel, cudaFuncAttributeMaxDynamicSharedMemorySize,
                         16384 * 4);

    prep_kernel<<<(ND + 255) / 256, 256>>>(bos, W, bias);
    pack_kernel<<<(XN + WN + 255) / 256, 256>>>(x, sl, W);
    xproj_hmma_kernel<<<dim3(28, 512), 256, 16384 * 4>>>(bias);
    recur_kernel<<<GRID_R, NTR, SMEM_RECUR>>>(W, dt, sl, out, out_final);
}

// round 14
// speedup vs baseline: 1.7039x; 1.0362x over previous
#include <cuda_runtime.h>
#include <cuda_fp16.h>
#include <math.h>
#include <stdint.h>

// Problem constants (ContTimeLSTM_66623532695635)
#define Bsz 128
#define Lseq 512
#define Iin 256
#define Dh 512
#define ND 3584          // 7*D
#define FIN 768          // I + D
#define BD (Bsz*Dh)      // 65536

#define GRID_R 128       // persistent recur blocks
#define NTR 512          // 16 warps: wm = w&3 (m16 group), wk = w>>2 (k quarter)

// ---------------- device scratch ----------------
// XP2 layout: [t][dn(64)][b(128)][gate(7)*8 + j]
__device__ float g_xp2[(size_t)Lseq * 64 * Bsz * 56];
__device__ uint32_t g_H16[2][BD / 2];                   // pure fp16 h, half2-packed (d pairs)
__device__ uint32_t g_x16[(size_t)Bsz * Lseq * Iin / 2]; // masked x, fp16 half2-packed
#define WFRAG_PLANE (28 * 16384)
__device__ uint32_t g_wfrag[WFRAG_PLANE];               // W x-part fragments (fp16)
__device__ float g_proj0[ND];
__device__ __align__(256) unsigned g_bar2[64];          // [0]: half 0, [32]: half 1

// ---- fast transcendentals (MUFU-based) ----
__device__ __forceinline__ float sigf(float x) {
    return __fdividef(1.0f, 1.0f + __expf(-x));
}
__device__ __forceinline__ float tanhf_fast(float x) {
    float xc = fminf(fmaxf(x, -15.0f), 15.0f);
    float e = __expf(2.0f * xc);
    return __fdividef(e - 1.0f, e + 1.0f);
}
__device__ __forceinline__ float softplusf(float x) {
    if (x > 0.0f) return x + __logf(1.0f + __expf(-x));
    return __logf(1.0f + __expf(x));
}
__device__ __forceinline__ unsigned ld_acq(unsigned* p) {
    unsigned v;
    asm volatile("ld.acquire.gpu.u32 %0, [%1];" : "=r"(v) : "l"(p) : "memory");
    return v;
}
__device__ __forceinline__ void red_rel_add1(unsigned* p) {
    asm volatile("red.release.gpu.global.add.u32 [%0], 1;" :: "l"(p) : "memory");
}
__device__ __forceinline__ uint32_t pack2h(__half a, __half b) {
    return ((uint32_t)__half_as_ushort(b) << 16) | __half_as_ushort(a);
}

#define MMA_F16(d, a, b0, b1) \
    asm volatile("mma.sync.aligned.m16n8k16.row.col.f32.f16.f16.f32 " \
        "{%0,%1,%2,%3}, {%4,%5,%6,%7}, {%8,%9}, {%0,%1,%2,%3};" \
        : "+f"((d)[0]), "+f"((d)[1]), "+f"((d)[2]), "+f"((d)[3]) \
        : "r"((a)[0]), "r"((a)[1]), "r"((a)[2]), "r"((a)[3]), "r"(b0), "r"(b1))

// ---------------- launch 1: reset barriers + proj0 ----------------
__global__ void prep_kernel(const float* __restrict__ bos,
                            const float* __restrict__ W,
                            const float* __restrict__ bias) {
    int n = blockIdx.x * blockDim.x + threadIdx.x;
    if (n == 0) { g_bar2[0] = 0u; g_bar2[32] = 0u; }
    if (n >= ND) return;
    const float* wrow = W + (size_t)n * FIN;
    float acc = bias[n];
    #pragma unroll 8
    for (int i = 0; i < Iin; i++) acc += bos[i] * wrow[i];
    g_proj0[n] = acc;
}

// ---------------- launch 2: pack x (masked, fp16 pairs) + W x-part fragments ----------------
#define XN2 (Bsz * Lseq * Iin / 2)     // 8,388,608 u32
#define WN (28 * 16 * 16 * 32)         // 229,376
__global__ void pack_kernel(const float* __restrict__ x,
                            const int* __restrict__ sl,
                            const float* __restrict__ W) {
    int idx = blockIdx.x * blockDim.x + threadIdx.x;
    if (idx < XN2) {
        int row = idx >> 7;            // /128 (u32 per row)
        int iu = idx & 127;
        int t = row >> 7;
        int b = row & 127;
        float v0 = 0.0f, v1 = 0.0f;
        if (t < __ldg(sl + b)) {
            const float* xp = x + ((size_t)b * Lseq + t) * Iin + iu * 2;
            v0 = xp[0]; v1 = xp[1];
        }
        g_x16[idx] = pack2h(__float2half_rn(v0), __float2half_rn(v1));
        return;
    }
    int e = idx - XN2;
    if (e >= WN) return;
    int lane = e & 31;
    int nt = (e >> 5) & 15;
    int ks = (e >> 9) & 15;
    int nb = e >> 13;
    int gg = lane >> 2, tt = lane & 3;
    int n = nb * 128 + nt * 8 + gg;
    const float* wr = W + (size_t)n * FIN + ks * 16 + tt * 2;
    __half h0 = __float2half_rn(wr[0]), h1 = __float2half_rn(wr[1]);
    __half h2 = __float2half_rn(wr[8]), h3 = __float2half_rn(wr[9]);
    size_t base = (size_t)e * 2;
    g_wfrag[base] = pack2h(h0, h1);
    g_wfrag[base + 1] = pack2h(h2, h3);
}

// ---------------- launch 3: XP = mask(x) @ Wx^T + bias via HMMA (fp16, 1-pass) ----------------
__global__ __launch_bounds__(256, 1)
void xproj_hmma_kernel(const float* __restrict__ bias) {
    extern __shared__ uint32_t sW[];   // 16384 u32 = 64 KB
    const int tid = threadIdx.x;
    const int w = tid >> 5, lane = tid & 31;
    const int g = lane >> 2, tq = lane & 3;
    const int nb = blockIdx.x, mb = blockIdx.y;

    {
        const uint4* src = (const uint4*)(g_wfrag + (size_t)nb * 16384);
        uint4* dst = (uint4*)sW;
        #pragma unroll
        for (int i = 0; i < 16; i++) dst[tid + i * 256] = src[tid + i * 256];
    }
    __syncthreads();

    const int r0 = mb * 128 + w * 16 + g;
    const uint32_t* x0p = g_x16 + (size_t)r0 * 128;        // 128 u32 per row
    const uint32_t* x1p = g_x16 + (size_t)(r0 + 8) * 128;

    float acc[16][4];
    #pragma unroll
    for (int nt = 0; nt < 16; nt++) {
        int n = nb * 128 + nt * 8 + tq * 2;
        float b0 = __ldg(bias + n), b1 = __ldg(bias + n + 1);
        acc[nt][0] = b0; acc[nt][1] = b1; acc[nt][2] = b0; acc[nt][3] = b1;
    }

    // ring-2 A prefetch: a[0]=r0@k, a[1]=r1@k, a[2]=r0@k+8, a[3]=r1@k+8 (u32 = half2)
    uint32_t ring[2][4];
    #pragma unroll
    for (int p = 0; p < 2; p++) {
        int ku = p * 8 + tq;           // u32 index within row
        ring[p][0] = x0p[ku];
        ring[p][1] = x1p[ku];
        ring[p][2] = x0p[ku + 4];
        ring[p][3] = x1p[ku + 4];
    }

    #pragma unroll 2
    for (int ks = 0; ks < 16; ks++) {
        int slot = ks & 1;
        uint32_t a[4] = {ring[slot][0], ring[slot][1], ring[slot][2], ring[slot][3]};
        if (ks + 2 < 16) {
            int ku = (ks + 2) * 8 + tq;
            ring[slot][0] = x0p[ku];
            ring[slot][1] = x1p[ku];
            ring[slot][2] = x0p[ku + 4];
            ring[slot][3] = x1p[ku + 4];
        }
        #pragma unroll
        for (int nt = 0; nt < 16; nt++) {
            uint2 vh = *(const uint2*)(sW + ((ks * 16 + nt) * 32 + lane) * 2);
            MMA_F16(acc[nt], a, vh.x, vh.y);
        }
    }

    // epilogue: write into XP2 layout [t][dn][b][gate*8 + j]
    const int tt0 = r0 >> 7;
    const int b0 = r0 & 127;
    #pragma unroll
    for (int nt = 0; nt < 16; nt++) {
        int n = nb * 128 + nt * 8 + tq * 2;
        int gate = n >> 9;
        int dloc = n & 511;
        int dnx = dloc >> 3;
        size_t base = (((size_t)tt0 * 64 + dnx) * 128);
        size_t off = gate * 8 + (dloc & 7);
        *(float2*)&g_xp2[(base + b0) * 56 + off]     = make_float2(acc[nt][0], acc[nt][1]);
        *(float2*)&g_xp2[(base + b0 + 8) * 56 + off] = make_float2(acc[nt][2], acc[nt][3]);
    }
}

// ================= launch 4: persistent recurrence (fp16 1-pass) =================
#define NFRAG 224                    // 32 ks * 7 nt
#define SB_U32 (NFRAG * 32 * 2)      // 14336 u32 = 57344 B
#define RED_STRIDE 29                // odd stride -> conflict-free; SCALAR access only
#define SRED_FLOATS (3 * 128 * RED_STRIDE)
#define SMEM_RECUR (SB_U32 * 4 + SRED_FLOATS * 4)

__global__ __launch_bounds__(NTR, 1)
void recur_kernel(const float* __restrict__ W,
                  const float* __restrict__ dt,
                  const int* __restrict__ sl,
                  float* __restrict__ out_h,
                  float* __restrict__ out_final) {
    extern __shared__ uint32_t sB[];
    float* sRed = (float*)(sB + SB_U32);

    const int tid = threadIdx.x;
    const int w = tid >> 5;
    const int lane = tid & 31;
    const int g = lane >> 2;
    const int tq = lane & 3;
    const int wm = w & 3;            // m16 group (0..3)
    const int wk = w >> 2;           // k quarter (0..3)
    const int dn = blockIdx.x >> 1;
    const int bh = blockIdx.x & 1;
    const int d0 = dn * 8 + tq * 2;
    unsigned* barp = &g_bar2[bh * 32];

    // ---- pack W h-part fragments (fp16) ----
    for (int e = tid; e < NFRAG * 32; e += NTR) {
        int f = e >> 5;
        int l = e & 31;
        int ks = f / 7, nt = f % 7;
        int gg = l >> 2, tt = l & 3;
        int n = nt * Dh + dn * 8 + gg;
        const float* wr = W + (size_t)n * FIN + Iin + ks * 16;
        __half h0 = __float2half_rn(wr[tt * 2]),     h1 = __float2half_rn(wr[tt * 2 + 1]);
        __half h2 = __float2half_rn(wr[tt * 2 + 8]), h3 = __float2half_rn(wr[tt * 2 + 9]);
        uint32_t* p = sB + (size_t)e * 2;
        p[0] = pack2h(h0, h1);
        p[1] = pack2h(h2, h3);
    }

    int rows[2];
    rows[0] = bh * 64 + wm * 16 + g;
    rows[1] = rows[0] + 8;

    int lenr[2] = {0, 0};
    float stC[2][2], stCe[2][2];

    if (wk == 0) {
        #pragma unroll
        for (int rh = 0; rh < 2; rh++) {
            int b = rows[rh];
            lenr[rh] = sl[b];
            float dtv = dt[b * Lseq + 0];
            float h2v[2];
            #pragma unroll
            for (int cj = 0; cj < 2; cj++) {
                int d = d0 + cj;
                float p0 = g_proj0[0 * Dh + d];
                float p2 = g_proj0[2 * Dh + d];
                float p4 = g_proj0[4 * Dh + d];
                float p5 = g_proj0[5 * Dh + d];
                float p6 = g_proj0[6 * Dh + d];
                float z   = tanhf_fast(p5);
                float cs0 = sigf(p0) * z;
                float ce0 = sigf(p2) * z;
                float o0  = sigf(p4);
                float dn0 = softplusf(p6);
                float c = ce0 + (cs0 - ce0) * __expf(-dn0 * dtv);
                float h = o0 * tanhf_fast(c);
                stC[rh][cj] = c;
                stCe[rh][cj] = ce0;
                h2v[cj] = h;
            }
            *(float2*)&out_h[((size_t)b * Lseq + 0) * Dh + d0] = make_float2(h2v[0], h2v[1]);
            g_H16[0][b * 256 + (d0 >> 1)] =
                pack2h(__float2half_rn(h2v[0]), __float2half_rn(h2v[1]));
        }
    }

    // acc: wk0 = XP2[0], others zero
    float acc[7][4];
    if (wk == 0) {
        const float* xb = g_xp2 + (((size_t)0 * 64 + dn) * 128) * 56;
        #pragma unroll
        for (int nt = 0; nt < 7; nt++) {
            float2 x0 = *(const float2*)(xb + (size_t)rows[0] * 56 + nt * 8 + tq * 2);
            float2 x1 = *(const float2*)(xb + (size_t)rows[1] * 56 + nt * 8 + tq * 2);
            acc[nt][0] = x0.x; acc[nt][1] = x0.y;
            acc[nt][2] = x1.x; acc[nt][3] = x1.y;
        }
    } else {
        #pragma unroll
        for (int nt = 0; nt < 7; nt++)
            #pragma unroll
            for (int ci = 0; ci < 4; ci++) acc[nt][ci] = 0.0f;
    }

    __syncthreads();                         // sB + h0 stores ordered block-wide
    if (tid == 0) red_rel_add1(barp);        // 1 arrival/block -> 64/half

    unsigned tgt = 64;
    if (tid == 0) { while (ld_acq(barp) < tgt) {} }
    __syncthreads();

    const int kubase = wk * 64;              // u32 index base (k quarter = 128 halves)

    for (int t = 0; t < Lseq; t++) {
        const uint32_t* Hs = g_H16[t & 1];
        const uint32_t* h0p = Hs + rows[0] * 256;
        const uint32_t* h1p = Hs + rows[1] * 256;

        // ring-2 A prefetch (u32 = half2 of 2 consecutive k)
        uint32_t ring[2][4];
        #pragma unroll
        for (int p = 0; p < 2; p++) {
            int ku = kubase + p * 8 + tq;
            ring[p][0] = h0p[ku];
            ring[p][1] = h1p[ku];
            ring[p][2] = h0p[ku + 4];
            ring[p][3] = h1p[ku + 4];
        }

        #pragma unroll 4
        for (int ks = 0; ks < 8; ks++) {
            int slot = ks & 1;
            uint32_t a[4] = {ring[slot][0], ring[slot][1], ring[slot][2], ring[slot][3]};
            if (ks + 2 < 8) {
                int ku = kubase + (ks + 2) * 8 + tq;
                ring[slot][0] = h0p[ku];
                ring[slot][1] = h1p[ku];
                ring[slot][2] = h0p[ku + 4];
                ring[slot][3] = h1p[ku + 4];
            }
            int gks = wk * 8 + ks;
            #pragma unroll
            for (int nt = 0; nt < 7; nt++) {
                uint2 bv = *(const uint2*)(sB + (size_t)((gks * 7 + nt) * 32 + lane) * 2);
                MMA_F16(acc[nt], a, bv.x, bv.y);
            }
        }

        if (wk != 0) {
            float* rp = sRed + (size_t)(((wk - 1) * 128) + wm * 32 + lane) * RED_STRIDE;
            #pragma unroll
            for (int nt = 0; nt < 7; nt++) {
                rp[nt * 4 + 0] = acc[nt][0];
                rp[nt * 4 + 1] = acc[nt][1];
                rp[nt * 4 + 2] = acc[nt][2];
                rp[nt * 4 + 3] = acc[nt][3];
            }
            #pragma unroll
            for (int nt = 0; nt < 7; nt++)
                #pragma unroll
                for (int ci = 0; ci < 4; ci++) acc[nt][ci] = 0.0f;
        }
        __syncthreads();                     // sRed visible

        if (wk == 0) {
            #pragma unroll
            for (int q = 0; q < 3; q++) {
                const float* rp = sRed + (size_t)(q * 128 + wm * 32 + lane) * RED_STRIDE;
                #pragma unroll
                for (int nt = 0; nt < 7; nt++) {
                    acc[nt][0] += rp[nt * 4 + 0];
                    acc[nt][1] += rp[nt * 4 + 1];
                    acc[nt][2] += rp[nt * 4 + 2];
                    acc[nt][3] += rp[nt * 4 + 3];
                }
            }
            // ---- epilogue: gates + state for 2 rows x 2 d ----
            #pragma unroll
            for (int rh = 0; rh < 2; rh++) {
                int b = rows[rh];
                int len = lenr[rh];
                float dtv = 0.0f;
                if (t + 1 < Lseq) dtv = ((t + 1) < len) ? dt[b * Lseq + t + 1] : 0.0f;
                float hn[2];
                #pragma unroll
                for (int cj = 0; cj < 2; cj++) {
                    int ci = rh * 2 + cj;
                    float i_g  = sigf(acc[0][ci]);
                    float f_g  = sigf(acc[1][ci]);
                    float ie_g = sigf(acc[2][ci]);
                    float fe_g = sigf(acc[3][ci]);
                    float o_n  = sigf(acc[4][ci]);
                    float z    = tanhf_fast(acc[5][ci]);
                    float d_n  = softplusf(acc[6][ci]);
                    float cs_n = f_g * stC[rh][cj] + i_g * z;
                    float ce_n = fe_g * stCe[rh][cj] + ie_g * z;
                    if (t == len - 1) {
                        float* f = out_final + (size_t)b * 4 * Dh + d0 + cj;
                        f[0 * Dh] = o_n;
                        f[1 * Dh] = cs_n;
                        f[2 * Dh] = ce_n;
                        f[3 * Dh] = d_n;
                    }
                    float cn = ce_n + (cs_n - ce_n) * __expf(-d_n * dtv);
                    float h = o_n * tanhf_fast(cn);
                    stC[rh][cj] = cn;
                    stCe[rh][cj] = ce_n;
                    hn[cj] = h;
                }
                if (t + 1 < Lseq) {
                    *(float2*)&out_h[((size_t)b * Lseq + (t + 1)) * Dh + d0] =
                        make_float2(hn[0], hn[1]);
                    g_H16[(t + 1) & 1][b * 256 + (d0 >> 1)] =
                        pack2h(__float2half_rn(hn[0]), __float2half_rn(hn[1]));
                }
            }
            if (t + 1 < Lseq) {
                // prefetch XP2[t+1] into acc (contiguous; hidden behind barrier wait)
                const float* xb = g_xp2 + (((size_t)(t + 1) * 64 + dn) * 128) * 56;
                #pragma unroll
                for (int nt = 0; nt < 7; nt++) {
                    float2 x0 = *(const float2*)(xb + (size_t)rows[0] * 56 + nt * 8 + tq * 2);
                    float2 x1 = *(const float2*)(xb + (size_t)rows[1] * 56 + nt * 8 + tq * 2);
                    acc[nt][0] = x0.x; acc[nt][1] = x0.y;
                    acc[nt][2] = x1.x; acc[nt][3] = x1.y;
                }
                asm volatile("bar.sync 1, 128;" ::: "memory");
                if (tid == 0) red_rel_add1(barp);   // publish h_{t+1}
            }
        }

        if (t + 1 < Lseq) {
            tgt += 64;
            if (tid == 0) { while (ld_acq(barp) < tgt) {} }
            __syncthreads();
        }
    }
}

// ---------------- launch ----------------
extern "C" void kernel_launch(void* const* d_in, const int* in_sizes, int n_in,
                              void* d_out, int out_size) {
    const float* x    = (const float*)d_in[0];   // (B,L,I)
    const float* dt   = (const float*)d_in[1];   // (B,L)
    const int*   sl   = (const int*)  d_in[2];   // (B,)
    const float* bos  = (const float*)d_in[3];   // (I,)
    const float* W    = (const float*)d_in[4];   // (7D, I+D)
    const float* bias = (const float*)d_in[5];   // (7D,)
    float* out = (float*)d_out;
    float* out_final = out + (size_t)Bsz * Lseq * Dh;

    cudaFuncSetAttribute(recur_kernel, cudaFuncAttributeMaxDynamicSharedMemorySize,
                         SMEM_RECUR);
    cudaFuncSetAttribute(xproj_hmma_kernel, cudaFuncAttributeMaxDynamicSharedMemorySize,
                         16384 * 4);

    prep_kernel<<<(ND + 255) / 256, 256>>>(bos, W, bias);
    pack_kernel<<<(XN2 + WN + 255) / 256, 256>>>(x, sl, W);
    xproj_hmma_kernel<<<dim3(28, 512), 256, 16384 * 4>>>(bias);
    recur_kernel<<<GRID_R, NTR, SMEM_RECUR>>>(W, dt, sl, out, out_final);
}

// round 15
// speedup vs baseline: 1.7171x; 1.0078x over previous
#include <cuda_runtime.h>
#include <cuda_fp16.h>
#include <math.h>
#include <stdint.h>

// Problem constants (ContTimeLSTM_66623532695635)
#define Bsz 128
#define Lseq 512
#define Iin 256
#define Dh 512
#define ND 3584          // 7*D
#define FIN 768          // I + D
#define BD (Bsz*Dh)      // 65536

#define GRID_R 256       // 2 bh x 64 dn x 2 mh; 2 blocks/SM (tail overlap)
#define NTR 256          // 8 warps: wm = w&1 (m16 group), wk = w>>1 (k quarter)

// ---------------- device scratch ----------------
// XP2 layout: [t][dn(64)][b(128)][gate(7)*8 + j]
__device__ float g_xp2[(size_t)Lseq * 64 * Bsz * 56];
__device__ uint32_t g_H16[2][BD / 2];                    // fp16 h, half2-packed
__device__ uint32_t g_x16[(size_t)Bsz * Lseq * Iin / 2]; // masked x, fp16 half2
#define WFRAG_PLANE (28 * 16384)
__device__ uint32_t g_wfrag[WFRAG_PLANE];                // W x-part fragments (fp16)
__device__ float g_proj0[ND];
__device__ __align__(256) unsigned g_bar2[64];           // [0]: half 0, [32]: half 1

// ---- fast transcendentals (MUFU-based) ----
__device__ __forceinline__ float sigf(float x) {
    return __fdividef(1.0f, 1.0f + __expf(-x));
}
__device__ __forceinline__ float tanhf_fast(float x) {
    float xc = fminf(fmaxf(x, -15.0f), 15.0f);
    float e = __expf(2.0f * xc);
    return __fdividef(e - 1.0f, e + 1.0f);
}
__device__ __forceinline__ float softplusf(float x) {
    if (x > 0.0f) return x + __logf(1.0f + __expf(-x));
    return __logf(1.0f + __expf(x));
}
__device__ __forceinline__ unsigned ld_acq(unsigned* p) {
    unsigned v;
    asm volatile("ld.acquire.gpu.u32 %0, [%1];" : "=r"(v) : "l"(p) : "memory");
    return v;
}
__device__ __forceinline__ void red_rel_add1(unsigned* p) {
    asm volatile("red.release.gpu.global.add.u32 [%0], 1;" :: "l"(p) : "memory");
}
__device__ __forceinline__ uint32_t pack2h(__half a, __half b) {
    return ((uint32_t)__half_as_ushort(b) << 16) | __half_as_ushort(a);
}

#define MMA_F16(d, a, b0, b1) \
    asm volatile("mma.sync.aligned.m16n8k16.row.col.f32.f16.f16.f32 " \
        "{%0,%1,%2,%3}, {%4,%5,%6,%7}, {%8,%9}, {%0,%1,%2,%3};" \
        : "+f"((d)[0]), "+f"((d)[1]), "+f"((d)[2]), "+f"((d)[3]) \
        : "r"((a)[0]), "r"((a)[1]), "r"((a)[2]), "r"((a)[3]), "r"(b0), "r"(b1))

// ---------------- launch 1: reset barriers + proj0 ----------------
__global__ void prep_kernel(const float* __restrict__ bos,
                            const float* __restrict__ W,
                            const float* __restrict__ bias) {
    int n = blockIdx.x * blockDim.x + threadIdx.x;
    if (n == 0) { g_bar2[0] = 0u; g_bar2[32] = 0u; }
    if (n >= ND) return;
    const float* wrow = W + (size_t)n * FIN;
    float acc = bias[n];
    #pragma unroll 8
    for (int i = 0; i < Iin; i++) acc += bos[i] * wrow[i];
    g_proj0[n] = acc;
}

// ---------------- launch 2: pack x (masked, fp16 pairs) + W x-part fragments ----------------
#define XN2 (Bsz * Lseq * Iin / 2)     // 8,388,608 u32
#define WN (28 * 16 * 16 * 32)         // 229,376
__global__ void pack_kernel(const float* __restrict__ x,
                            const int* __restrict__ sl,
                            const float* __restrict__ W) {
    int idx = blockIdx.x * blockDim.x + threadIdx.x;
    if (idx < XN2) {
        int row = idx >> 7;
        int iu = idx & 127;
        int t = row >> 7;
        int b = row & 127;
        float v0 = 0.0f, v1 = 0.0f;
        if (t < __ldg(sl + b)) {
            const float* xp = x + ((size_t)b * Lseq + t) * Iin + iu * 2;
            v0 = xp[0]; v1 = xp[1];
        }
        g_x16[idx] = pack2h(__float2half_rn(v0), __float2half_rn(v1));
        return;
    }
    int e = idx - XN2;
    if (e >= WN) return;
    int lane = e & 31;
    int nt = (e >> 5) & 15;
    int ks = (e >> 9) & 15;
    int nb = e >> 13;
    int gg = lane >> 2, tt = lane & 3;
    int n = nb * 128 + nt * 8 + gg;
    const float* wr = W + (size_t)n * FIN + ks * 16 + tt * 2;
    __half h0 = __float2half_rn(wr[0]), h1 = __float2half_rn(wr[1]);
    __half h2 = __float2half_rn(wr[8]), h3 = __float2half_rn(wr[9]);
    size_t base = (size_t)e * 2;
    g_wfrag[base] = pack2h(h0, h1);
    g_wfrag[base + 1] = pack2h(h2, h3);
}

// ---------------- launch 3: XP = mask(x) @ Wx^T + bias via HMMA (fp16, 1-pass) ----------------
__global__ __launch_bounds__(256, 1)
void xproj_hmma_kernel(const float* __restrict__ bias) {
    extern __shared__ uint32_t sW[];   // 16384 u32 = 64 KB
    const int tid = threadIdx.x;
    const int w = tid >> 5, lane = tid & 31;
    const int g = lane >> 2, tq = lane & 3;
    const int nb = blockIdx.x, mb = blockIdx.y;

    {
        const uint4* src = (const uint4*)(g_wfrag + (size_t)nb * 16384);
        uint4* dst = (uint4*)sW;
        #pragma unroll
        for (int i = 0; i < 16; i++) dst[tid + i * 256] = src[tid + i * 256];
    }
    __syncthreads();

    const int r0 = mb * 128 + w * 16 + g;
    const uint32_t* x0p = g_x16 + (size_t)r0 * 128;
    const uint32_t* x1p = g_x16 + (size_t)(r0 + 8) * 128;

    float acc[16][4];
    #pragma unroll
    for (int nt = 0; nt < 16; nt++) {
        int n = nb * 128 + nt * 8 + tq * 2;
        float b0 = __ldg(bias + n), b1 = __ldg(bias + n + 1);
        acc[nt][0] = b0; acc[nt][1] = b1; acc[nt][2] = b0; acc[nt][3] = b1;
    }

    uint32_t ring[2][4];
    #pragma unroll
    for (int p = 0; p < 2; p++) {
        int ku = p * 8 + tq;
        ring[p][0] = x0p[ku];
        ring[p][1] = x1p[ku];
        ring[p][2] = x0p[ku + 4];
        ring[p][3] = x1p[ku + 4];
    }

    #pragma unroll 2
    for (int ks = 0; ks < 16; ks++) {
        int slot = ks & 1;
        uint32_t a[4] = {ring[slot][0], ring[slot][1], ring[slot][2], ring[slot][3]};
        if (ks + 2 < 16) {
            int ku = (ks + 2) * 8 + tq;
            ring[slot][0] = x0p[ku];
            ring[slot][1] = x1p[ku];
            ring[slot][2] = x0p[ku + 4];
            ring[slot][3] = x1p[ku + 4];
        }
        #pragma unroll
        for (int nt = 0; nt < 16; nt++) {
            uint2 vh = *(const uint2*)(sW + ((ks * 16 + nt) * 32 + lane) * 2);
            MMA_F16(acc[nt], a, vh.x, vh.y);
        }
    }

    const int tt0 = r0 >> 7;
    const int b0 = r0 & 127;
    #pragma unroll
    for (int nt = 0; nt < 16; nt++) {
        int n = nb * 128 + nt * 8 + tq * 2;
        int gate = n >> 9;
        int dloc = n & 511;
        int dnx = dloc >> 3;
        size_t base = (((size_t)tt0 * 64 + dnx) * 128);
        size_t off = gate * 8 + (dloc & 7);
        *(float2*)&g_xp2[(base + b0) * 56 + off]     = make_float2(acc[nt][0], acc[nt][1]);
        *(float2*)&g_xp2[(base + b0 + 8) * 56 + off] = make_float2(acc[nt][2], acc[nt][3]);
    }
}

// ================= launch 4: persistent recurrence (fp16, 2 blocks/SM) =================
// 256 blocks = 2 bh (interleaved) x 64 dn x 2 mh. 8 warps = 2 wm (m16) x 4 wk (K=128).
#define NFRAG 224                    // 32 ks * 7 nt
#define SB_U32 (NFRAG * 32 * 2)      // 14336 u32 = 57344 B
#define RED_STRIDE 29                // odd stride -> conflict-free; SCALAR access
#define SRED_FLOATS (3 * 64 * RED_STRIDE)
#define SMEM_RECUR (SB_U32 * 4 + SRED_FLOATS * 4)   // 79616 B -> 2 blocks/SM

__global__ __launch_bounds__(NTR, 2)
void recur_kernel(const float* __restrict__ W,
                  const float* __restrict__ dt,
                  const int* __restrict__ sl,
                  float* __restrict__ out_h,
                  float* __restrict__ out_final) {
    extern __shared__ uint32_t sB[];
    float* sRed = (float*)(sB + SB_U32);

    const int tid = threadIdx.x;
    const int w = tid >> 5;
    const int lane = tid & 31;
    const int g = lane >> 2;
    const int tq = lane & 3;
    const int wm = w & 1;            // m16 group (0..1)
    const int wk = w >> 1;           // k quarter (0..3)
    const int bh = blockIdx.x & 1;   // batch half (interleaved across SMs)
    const int dn = (blockIdx.x >> 1) & 63;
    const int mh = blockIdx.x >> 7;  // m half (0..1)
    const int d0 = dn * 8 + tq * 2;
    unsigned* barp = &g_bar2[bh * 32];

    // ---- pack W h-part fragments (fp16) ----
    for (int e = tid; e < NFRAG * 32; e += NTR) {
        int f = e >> 5;
        int l = e & 31;
        int ks = f / 7, nt = f % 7;
        int gg = l >> 2, tt = l & 3;
        int n = nt * Dh + dn * 8 + gg;
        const float* wr = W + (size_t)n * FIN + Iin + ks * 16;
        __half h0 = __float2half_rn(wr[tt * 2]),     h1 = __float2half_rn(wr[tt * 2 + 1]);
        __half h2 = __float2half_rn(wr[tt * 2 + 8]), h3 = __float2half_rn(wr[tt * 2 + 9]);
        uint32_t* p = sB + (size_t)e * 2;
        p[0] = pack2h(h0, h1);
        p[1] = pack2h(h2, h3);
    }

    int rows[2];
    rows[0] = bh * 64 + mh * 32 + wm * 16 + g;
    rows[1] = rows[0] + 8;

    int lenr[2] = {0, 0};
    float stC[2][2], stCe[2][2];

    if (wk == 0) {
        #pragma unroll
        for (int rh = 0; rh < 2; rh++) {
            int b = rows[rh];
            lenr[rh] = sl[b];
            float dtv = dt[b * Lseq + 0];
            float h2v[2];
            #pragma unroll
            for (int cj = 0; cj < 2; cj++) {
                int d = d0 + cj;
                float p0 = g_proj0[0 * Dh + d];
                float p2 = g_proj0[2 * Dh + d];
                float p4 = g_proj0[4 * Dh + d];
                float p5 = g_proj0[5 * Dh + d];
                float p6 = g_proj0[6 * Dh + d];
                float z   = tanhf_fast(p5);
                float cs0 = sigf(p0) * z;
                float ce0 = sigf(p2) * z;
                float o0  = sigf(p4);
                float dn0 = softplusf(p6);
                float c = ce0 + (cs0 - ce0) * __expf(-dn0 * dtv);
                float h = o0 * tanhf_fast(c);
                stC[rh][cj] = c;
                stCe[rh][cj] = ce0;
                h2v[cj] = h;
            }
            *(float2*)&out_h[((size_t)b * Lseq + 0) * Dh + d0] = make_float2(h2v[0], h2v[1]);
            g_H16[0][b * 256 + (d0 >> 1)] =
                pack2h(__float2half_rn(h2v[0]), __float2half_rn(h2v[1]));
        }
    }

    // acc: wk0 = XP2[0], others zero
    float acc[7][4];
    if (wk == 0) {
        const float* xb = g_xp2 + (((size_t)0 * 64 + dn) * 128) * 56;
        #pragma unroll
        for (int nt = 0; nt < 7; nt++) {
            float2 x0 = *(const float2*)(xb + (size_t)rows[0] * 56 + nt * 8 + tq * 2);
            float2 x1 = *(const float2*)(xb + (size_t)rows[1] * 56 + nt * 8 + tq * 2);
            acc[nt][0] = x0.x; acc[nt][1] = x0.y;
            acc[nt][2] = x1.x; acc[nt][3] = x1.y;
        }
    } else {
        #pragma unroll
        for (int nt = 0; nt < 7; nt++)
            #pragma unroll
            for (int ci = 0; ci < 4; ci++) acc[nt][ci] = 0.0f;
    }

    __syncthreads();                         // sB + h0 stores ordered block-wide
    if (tid == 0) red_rel_add1(barp);        // 1 arrival/block -> 128/half

    unsigned tgt = 128;
    if (tid == 0) { while (ld_acq(barp) < tgt) {} }
    __syncthreads();

    const int kubase = wk * 64;              // u32 index base for k quarter

    for (int t = 0; t < Lseq; t++) {
        const uint32_t* Hs = g_H16[t & 1];
        const uint32_t* h0p = Hs + rows[0] * 256;
        const uint32_t* h1p = Hs + rows[1] * 256;

        uint32_t ring[2][4];
        #pragma unroll
        for (int p = 0; p < 2; p++) {
            int ku = kubase + p * 8 + tq;
            ring[p][0] = h0p[ku];
            ring[p][1] = h1p[ku];
            ring[p][2] = h0p[ku + 4];
            ring[p][3] = h1p[ku + 4];
        }

        #pragma unroll 4
        for (int ks = 0; ks < 8; ks++) {
            int slot = ks & 1;
            uint32_t a[4] = {ring[slot][0], ring[slot][1], ring[slot][2], ring[slot][3]};
            if (ks + 2 < 8) {
                int ku = kubase + (ks + 2) * 8 + tq;
                ring[slot][0] = h0p[ku];
                ring[slot][1] = h1p[ku];
                ring[slot][2] = h0p[ku + 4];
                ring[slot][3] = h1p[ku + 4];
            }
            int gks = wk * 8 + ks;
            #pragma unroll
            for (int nt = 0; nt < 7; nt++) {
                uint2 bv = *(const uint2*)(sB + (size_t)((gks * 7 + nt) * 32 + lane) * 2);
                MMA_F16(acc[nt], a, bv.x, bv.y);
            }
        }

        if (wk != 0) {
            float* rp = sRed + (size_t)(((wk - 1) * 64) + wm * 32 + lane) * RED_STRIDE;
            #pragma unroll
            for (int nt = 0; nt < 7; nt++) {
                rp[nt * 4 + 0] = acc[nt][0];
                rp[nt * 4 + 1] = acc[nt][1];
                rp[nt * 4 + 2] = acc[nt][2];
                rp[nt * 4 + 3] = acc[nt][3];
            }
            #pragma unroll
            for (int nt = 0; nt < 7; nt++)
                #pragma unroll
                for (int ci = 0; ci < 4; ci++) acc[nt][ci] = 0.0f;
        }
        __syncthreads();                     // sRed visible

        if (wk == 0) {
            #pragma unroll
            for (int q = 0; q < 3; q++) {
                const float* rp = sRed + (size_t)(q * 64 + wm * 32 + lane) * RED_STRIDE;
                #pragma unroll
                for (int nt = 0; nt < 7; nt++) {
                    acc[nt][0] += rp[nt * 4 + 0];
                    acc[nt][1] += rp[nt * 4 + 1];
                    acc[nt][2] += rp[nt * 4 + 2];
                    acc[nt][3] += rp[nt * 4 + 3];
                }
            }
            // ---- epilogue: gates + state for 2 rows x 2 d ----
            #pragma unroll
            for (int rh = 0; rh < 2; rh++) {
                int b = rows[rh];
                int len = lenr[rh];
                float dtv = 0.0f;
                if (t + 1 < Lseq) dtv = ((t + 1) < len) ? dt[b * Lseq + t + 1] : 0.0f;
                float hn[2];
                #pragma unroll
                for (int cj = 0; cj < 2; cj++) {
                    int ci = rh * 2 + cj;
                    float i_g  = sigf(acc[0][ci]);
                    float f_g  = sigf(acc[1][ci]);
                    float ie_g = sigf(acc[2][ci]);
                    float fe_g = sigf(acc[3][ci]);
                    float o_n  = sigf(acc[4][ci]);
                    float z    = tanhf_fast(acc[5][ci]);
                    float d_n  = softplusf(acc[6][ci]);
                    float cs_n = f_g * stC[rh][cj] + i_g * z;
                    float ce_n = fe_g * stCe[rh][cj] + ie_g * z;
                    if (t == len - 1) {
                        float* f = out_final + (size_t)b * 4 * Dh + d0 + cj;
                        f[0 * Dh] = o_n;
                        f[1 * Dh] = cs_n;
                        f[2 * Dh] = ce_n;
                        f[3 * Dh] = d_n;
                    }
                    float cn = ce_n + (cs_n - ce_n) * __expf(-d_n * dtv);
                    float h = o_n * tanhf_fast(cn);
                    stC[rh][cj] = cn;
                    stCe[rh][cj] = ce_n;
                    hn[cj] = h;
                }
                if (t + 1 < Lseq) {
                    *(float2*)&out_h[((size_t)b * Lseq + (t + 1)) * Dh + d0] =
                        make_float2(hn[0], hn[1]);
                    g_H16[(t + 1) & 1][b * 256 + (d0 >> 1)] =
                        pack2h(__float2half_rn(hn[0]), __float2half_rn(hn[1]));
                }
            }
            if (t + 1 < Lseq) {
                // prefetch XP2[t+1] into acc (hidden behind barrier wait)
                const float* xb = g_xp2 + (((size_t)(t + 1) * 64 + dn) * 128) * 56;
                #pragma unroll
                for (int nt = 0; nt < 7; nt++) {
                    float2 x0 = *(const float2*)(xb + (size_t)rows[0] * 56 + nt * 8 + tq * 2);
                    float2 x1 = *(const float2*)(xb + (size_t)rows[1] * 56 + nt * 8 + tq * 2);
                    acc[nt][0] = x0.x; acc[nt][1] = x0.y;
                    acc[nt][2] = x1.x; acc[nt][3] = x1.y;
                }
                // wk0 warps (threads 0..63) sync, then single arrival
                asm volatile("bar.sync 1, 64;" ::: "memory");
                if (tid == 0) red_rel_add1(barp);   // publish h_{t+1}
            }
        }

        if (t + 1 < Lseq) {
            tgt += 128;
            if (tid == 0) { while (ld_acq(barp) < tgt) {} }
            __syncthreads();
        }
    }
}

// ---------------- launch ----------------
extern "C" void kernel_launch(void* const* d_in, const int* in_sizes, int n_in,
                              void* d_out, int out_size) {
    const float* x    = (const float*)d_in[0];   // (B,L,I)
    const float* dt   = (const float*)d_in[1];   // (B,L)
    const int*   sl   = (const int*)  d_in[2];   // (B,)
    const float* bos  = (const float*)d_in[3];   // (I,)
    const float* W    = (const float*)d_in[4];   // (7D, I+D)
    const float* bias = (const float*)d_in[5];   // (7D,)
    float* out = (float*)d_out;
    float* out_final = out + (size_t)Bsz * Lseq * Dh;

    cudaFuncSetAttribute(recur_kernel, cudaFuncAttributeMaxDynamicSharedMemorySize,
                         SMEM_RECUR);
    cudaFuncSetAttribute(xproj_hmma_kernel, cudaFuncAttributeMaxDynamicSharedMemorySize,
                         16384 * 4);

    prep_kernel<<<(ND + 255) / 256, 256>>>(bos, W, bias);
    pack_kernel<<<(XN2 + WN + 255) / 256, 256>>>(x, sl, W);
    xproj_hmma_kernel<<<dim3(28, 512), 256, 16384 * 4>>>(bias);
    recur_kernel<<<GRID_R, NTR, SMEM_RECUR>>>(W, dt, sl, out, out_final);
}

// round 16
// speedup vs baseline: 1.7266x; 1.0055x over previous
#include <cuda_runtime.h>
#include <cuda_fp16.h>
#include <math.h>
#include <stdint.h>

// Problem constants (ContTimeLSTM_66623532695635)
#define Bsz 128
#define Lseq 512
#define Iin 256
#define Dh 512
#define ND 3584          // 7*D
#define FIN 768          // I + D
#define BD (Bsz*Dh)      // 65536

#define GRID_R 256       // 2 bh x 64 dn x 2 mh; 2 blocks/SM (tail overlap)
#define NTR 256          // 8 warps: wm = w&1 (m16 group), wk = w>>1 (k quarter)
#define SKEW_CYC 5000    // anti-phase skew for bh=1 (about half a step)

// ---------------- device scratch ----------------
// XP2 layout: [t][dn(64)][b(128)][gate(7)*8 + j]
__device__ float g_xp2[(size_t)Lseq * 64 * Bsz * 56];
__device__ uint32_t g_H16[2][BD / 2];                    // fp16 h, half2-packed
__device__ uint32_t g_x16[(size_t)Bsz * Lseq * Iin / 2]; // masked x, fp16 half2
#define WFRAG_PLANE (28 * 16384)
__device__ uint32_t g_wfrag[WFRAG_PLANE];                // W x-part fragments (fp16)
__device__ float g_proj0[ND];
__device__ __align__(256) unsigned g_bar2[64];           // [0]: half 0, [32]: half 1

// ---- fast transcendentals (MUFU-based) ----
__device__ __forceinline__ float sigf(float x) {
    return __fdividef(1.0f, 1.0f + __expf(-x));
}
__device__ __forceinline__ float tanhf_fast(float x) {
    float xc = fminf(fmaxf(x, -15.0f), 15.0f);
    float e = __expf(2.0f * xc);
    return __fdividef(e - 1.0f, e + 1.0f);
}
__device__ __forceinline__ float softplusf(float x) {
    if (x > 0.0f) return x + __logf(1.0f + __expf(-x));
    return __logf(1.0f + __expf(x));
}
__device__ __forceinline__ unsigned ld_acq(unsigned* p) {
    unsigned v;
    asm volatile("ld.acquire.gpu.u32 %0, [%1];" : "=r"(v) : "l"(p) : "memory");
    return v;
}
__device__ __forceinline__ void red_rel_add1(unsigned* p) {
    asm volatile("red.release.gpu.global.add.u32 [%0], 1;" :: "l"(p) : "memory");
}
__device__ __forceinline__ uint32_t pack2h(__half a, __half b) {
    return ((uint32_t)__half_as_ushort(b) << 16) | __half_as_ushort(a);
}

#define MMA_F16(d, a, b0, b1) \
    asm volatile("mma.sync.aligned.m16n8k16.row.col.f32.f16.f16.f32 " \
        "{%0,%1,%2,%3}, {%4,%5,%6,%7}, {%8,%9}, {%0,%1,%2,%3};" \
        : "+f"((d)[0]), "+f"((d)[1]), "+f"((d)[2]), "+f"((d)[3]) \
        : "r"((a)[0]), "r"((a)[1]), "r"((a)[2]), "r"((a)[3]), "r"(b0), "r"(b1))

// ---------------- launch 1: reset barriers + proj0 ----------------
__global__ void prep_kernel(const float* __restrict__ bos,
                            const float* __restrict__ W,
                            const float* __restrict__ bias) {
    int n = blockIdx.x * blockDim.x + threadIdx.x;
    if (n == 0) { g_bar2[0] = 0u; g_bar2[32] = 0u; }
    if (n >= ND) return;
    const float* wrow = W + (size_t)n * FIN;
    float acc = bias[n];
    #pragma unroll 8
    for (int i = 0; i < Iin; i++) acc += bos[i] * wrow[i];
    g_proj0[n] = acc;
}

// ---------------- launch 2: pack x (masked, fp16 pairs) + W x-part fragments ----------------
#define XN2 (Bsz * Lseq * Iin / 2)     // 8,388,608 u32
#define WN (28 * 16 * 16 * 32)         // 229,376
__global__ void pack_kernel(const float* __restrict__ x,
                            const int* __restrict__ sl,
                            const float* __restrict__ W) {
    int idx = blockIdx.x * blockDim.x + threadIdx.x;
    if (idx < XN2) {
        int row = idx >> 7;
        int iu = idx & 127;
        int t = row >> 7;
        int b = row & 127;
        float v0 = 0.0f, v1 = 0.0f;
        if (t < __ldg(sl + b)) {
            const float* xp = x + ((size_t)b * Lseq + t) * Iin + iu * 2;
            v0 = xp[0]; v1 = xp[1];
        }
        g_x16[idx] = pack2h(__float2half_rn(v0), __float2half_rn(v1));
        return;
    }
    int e = idx - XN2;
    if (e >= WN) return;
    int lane = e & 31;
    int nt = (e >> 5) & 15;
    int ks = (e >> 9) & 15;
    int nb = e >> 13;
    int gg = lane >> 2, tt = lane & 3;
    int n = nb * 128 + nt * 8 + gg;
    const float* wr = W + (size_t)n * FIN + ks * 16 + tt * 2;
    __half h0 = __float2half_rn(wr[0]), h1 = __float2half_rn(wr[1]);
    __half h2 = __float2half_rn(wr[8]), h3 = __float2half_rn(wr[9]);
    size_t base = (size_t)e * 2;
    g_wfrag[base] = pack2h(h0, h1);
    g_wfrag[base + 1] = pack2h(h2, h3);
}

// ---------------- launch 3: XP = mask(x) @ Wx^T + bias via HMMA (fp16, 1-pass) ----------------
__global__ __launch_bounds__(256, 1)
void xproj_hmma_kernel(const float* __restrict__ bias) {
    extern __shared__ uint32_t sW[];   // 16384 u32 = 64 KB
    const int tid = threadIdx.x;
    const int w = tid >> 5, lane = tid & 31;
    const int g = lane >> 2, tq = lane & 3;
    const int nb = blockIdx.x, mb = blockIdx.y;

    {
        const uint4* src = (const uint4*)(g_wfrag + (size_t)nb * 16384);
        uint4* dst = (uint4*)sW;
        #pragma unroll
        for (int i = 0; i < 16; i++) dst[tid + i * 256] = src[tid + i * 256];
    }
    __syncthreads();

    const int r0 = mb * 128 + w * 16 + g;
    const uint32_t* x0p = g_x16 + (size_t)r0 * 128;
    const uint32_t* x1p = g_x16 + (size_t)(r0 + 8) * 128;

    float acc[16][4];
    #pragma unroll
    for (int nt = 0; nt < 16; nt++) {
        int n = nb * 128 + nt * 8 + tq * 2;
        float b0 = __ldg(bias + n), b1 = __ldg(bias + n + 1);
        acc[nt][0] = b0; acc[nt][1] = b1; acc[nt][2] = b0; acc[nt][3] = b1;
    }

    uint32_t ring[2][4];
    #pragma unroll
    for (int p = 0; p < 2; p++) {
        int ku = p * 8 + tq;
        ring[p][0] = x0p[ku];
        ring[p][1] = x1p[ku];
        ring[p][2] = x0p[ku + 4];
        ring[p][3] = x1p[ku + 4];
    }

    #pragma unroll 2
    for (int ks = 0; ks < 16; ks++) {
        int slot = ks & 1;
        uint32_t a[4] = {ring[slot][0], ring[slot][1], ring[slot][2], ring[slot][3]};
        if (ks + 2 < 16) {
            int ku = (ks + 2) * 8 + tq;
            ring[slot][0] = x0p[ku];
            ring[slot][1] = x1p[ku];
            ring[slot][2] = x0p[ku + 4];
            ring[slot][3] = x1p[ku + 4];
        }
        #pragma unroll
        for (int nt = 0; nt < 16; nt++) {
            uint2 vh = *(const uint2*)(sW + ((ks * 16 + nt) * 32 + lane) * 2);
            MMA_F16(acc[nt], a, vh.x, vh.y);
        }
    }

    const int tt0 = r0 >> 7;
    const int b0 = r0 & 127;
    #pragma unroll
    for (int nt = 0; nt < 16; nt++) {
        int n = nb * 128 + nt * 8 + tq * 2;
        int gate = n >> 9;
        int dloc = n & 511;
        int dnx = dloc >> 3;
        size_t base = (((size_t)tt0 * 64 + dnx) * 128);
        size_t off = gate * 8 + (dloc & 7);
        *(float2*)&g_xp2[(base + b0) * 56 + off]     = make_float2(acc[nt][0], acc[nt][1]);
        *(float2*)&g_xp2[(base + b0 + 8) * 56 + off] = make_float2(acc[nt][2], acc[nt][3]);
    }
}

// ================= launch 4: persistent recurrence (fp16, 2 blocks/SM, anti-phase) =================
#define NFRAG 224                    // 32 ks * 7 nt
#define SB_U32 (NFRAG * 32 * 2)      // 14336 u32 = 57344 B
#define RED_STRIDE 29                // odd stride -> conflict-free; SCALAR access
#define SRED_FLOATS (3 * 64 * RED_STRIDE)
#define SMEM_RECUR (SB_U32 * 4 + SRED_FLOATS * 4)   // 79616 B -> 2 blocks/SM

__global__ __launch_bounds__(NTR, 2)
void recur_kernel(const float* __restrict__ W,
                  const float* __restrict__ dt,
                  const int* __restrict__ sl,
                  float* __restrict__ out_h,
                  float* __restrict__ out_final) {
    extern __shared__ uint32_t sB[];
    float* sRed = (float*)(sB + SB_U32);

    const int tid = threadIdx.x;
    const int w = tid >> 5;
    const int lane = tid & 31;
    const int g = lane >> 2;
    const int tq = lane & 3;
    const int wm = w & 1;            // m16 group (0..1)
    const int wk = w >> 1;           // k quarter (0..3)
    const int bh = blockIdx.x & 1;   // batch half (interleaved across SMs)
    const int dn = (blockIdx.x >> 1) & 63;
    const int mh = blockIdx.x >> 7;  // m half (0..1)
    const int d0 = dn * 8 + tq * 2;
    unsigned* barp = &g_bar2[bh * 32];

    // ---- pack W h-part fragments (fp16) ----
    for (int e = tid; e < NFRAG * 32; e += NTR) {
        int f = e >> 5;
        int l = e & 31;
        int ks = f / 7, nt = f % 7;
        int gg = l >> 2, tt = l & 3;
        int n = nt * Dh + dn * 8 + gg;
        const float* wr = W + (size_t)n * FIN + Iin + ks * 16;
        __half h0 = __float2half_rn(wr[tt * 2]),     h1 = __float2half_rn(wr[tt * 2 + 1]);
        __half h2 = __float2half_rn(wr[tt * 2 + 8]), h3 = __float2half_rn(wr[tt * 2 + 9]);
        uint32_t* p = sB + (size_t)e * 2;
        p[0] = pack2h(h0, h1);
        p[1] = pack2h(h2, h3);
    }

    int rows[2];
    rows[0] = bh * 64 + mh * 32 + wm * 16 + g;
    rows[1] = rows[0] + 8;

    int lenr[2] = {0, 0};
    float stC[2][2], stCe[2][2];

    if (wk == 0) {
        #pragma unroll
        for (int rh = 0; rh < 2; rh++) {
            int b = rows[rh];
            lenr[rh] = sl[b];
            float dtv = dt[b * Lseq + 0];
            float h2v[2];
            #pragma unroll
            for (int cj = 0; cj < 2; cj++) {
                int d = d0 + cj;
                float p0 = g_proj0[0 * Dh + d];
                float p2 = g_proj0[2 * Dh + d];
                float p4 = g_proj0[4 * Dh + d];
                float p5 = g_proj0[5 * Dh + d];
                float p6 = g_proj0[6 * Dh + d];
                float z   = tanhf_fast(p5);
                float cs0 = sigf(p0) * z;
                float ce0 = sigf(p2) * z;
                float o0  = sigf(p4);
                float dn0 = softplusf(p6);
                float c = ce0 + (cs0 - ce0) * __expf(-dn0 * dtv);
                float h = o0 * tanhf_fast(c);
                stC[rh][cj] = c;
                stCe[rh][cj] = ce0;
                h2v[cj] = h;
            }
            *(float2*)&out_h[((size_t)b * Lseq + 0) * Dh + d0] = make_float2(h2v[0], h2v[1]);
            g_H16[0][b * 256 + (d0 >> 1)] =
                pack2h(__float2half_rn(h2v[0]), __float2half_rn(h2v[1]));
        }
    }

    // acc: wk0 = XP2[0], others zero
    float acc[7][4];
    if (wk == 0) {
        const float* xb = g_xp2 + (((size_t)0 * 64 + dn) * 128) * 56;
        #pragma unroll
        for (int nt = 0; nt < 7; nt++) {
            float2 x0 = *(const float2*)(xb + (size_t)rows[0] * 56 + nt * 8 + tq * 2);
            float2 x1 = *(const float2*)(xb + (size_t)rows[1] * 56 + nt * 8 + tq * 2);
            acc[nt][0] = x0.x; acc[nt][1] = x0.y;
            acc[nt][2] = x1.x; acc[nt][3] = x1.y;
        }
    } else {
        #pragma unroll
        for (int nt = 0; nt < 7; nt++)
            #pragma unroll
            for (int ci = 0; ci < 4; ci++) acc[nt][ci] = 0.0f;
    }

    __syncthreads();                         // sB + h0 stores ordered block-wide
    if (tid == 0) red_rel_add1(barp);        // 1 arrival/block -> 128/half

    unsigned tgt = 128;
    if (tid == 0) { while (ld_acq(barp) < tgt) {} }
    __syncthreads();

    // ---- anti-phase skew: offset half 1 by ~half a step so co-resident
    // blocks from opposite halves time-multiplex the SM (tail overlap) ----
    if (bh == 1) {
        long long s0 = clock64();
        while (clock64() - s0 < SKEW_CYC) {}
    }

    const int kubase = wk * 64;              // u32 index base for k quarter

    for (int t = 0; t < Lseq; t++) {
        const uint32_t* Hs = g_H16[t & 1];
        const uint32_t* h0p = Hs + rows[0] * 256;
        const uint32_t* h1p = Hs + rows[1] * 256;

        uint32_t ring[2][4];
        #pragma unroll
        for (int p = 0; p < 2; p++) {
            int ku = kubase + p * 8 + tq;
            ring[p][0] = h0p[ku];
            ring[p][1] = h1p[ku];
            ring[p][2] = h0p[ku + 4];
            ring[p][3] = h1p[ku + 4];
        }

        #pragma unroll 4
        for (int ks = 0; ks < 8; ks++) {
            int slot = ks & 1;
            uint32_t a[4] = {ring[slot][0], ring[slot][1], ring[slot][2], ring[slot][3]};
            if (ks + 2 < 8) {
                int ku = kubase + (ks + 2) * 8 + tq;
                ring[slot][0] = h0p[ku];
                ring[slot][1] = h1p[ku];
                ring[slot][2] = h0p[ku + 4];
                ring[slot][3] = h1p[ku + 4];
            }
            int gks = wk * 8 + ks;
            #pragma unroll
            for (int nt = 0; nt < 7; nt++) {
                uint2 bv = *(const uint2*)(sB + (size_t)((gks * 7 + nt) * 32 + lane) * 2);
                MMA_F16(acc[nt], a, bv.x, bv.y);
            }
        }

        if (wk != 0) {
            float* rp = sRed + (size_t)(((wk - 1) * 64) + wm * 32 + lane) * RED_STRIDE;
            #pragma unroll
            for (int nt = 0; nt < 7; nt++) {
                rp[nt * 4 + 0] = acc[nt][0];
                rp[nt * 4 + 1] = acc[nt][1];
                rp[nt * 4 + 2] = acc[nt][2];
                rp[nt * 4 + 3] = acc[nt][3];
            }
            #pragma unroll
            for (int nt = 0; nt < 7; nt++)
                #pragma unroll
                for (int ci = 0; ci < 4; ci++) acc[nt][ci] = 0.0f;
        }
        __syncthreads();                     // sRed visible

        if (wk == 0) {
            #pragma unroll
            for (int q = 0; q < 3; q++) {
                const float* rp = sRed + (size_t)(q * 64 + wm * 32 + lane) * RED_STRIDE;
                #pragma unroll
                for (int nt = 0; nt < 7; nt++) {
                    acc[nt][0] += rp[nt * 4 + 0];
                    acc[nt][1] += rp[nt * 4 + 1];
                    acc[nt][2] += rp[nt * 4 + 2];
                    acc[nt][3] += rp[nt * 4 + 3];
                }
            }
            // ---- epilogue: gates + state for 2 rows x 2 d ----
            #pragma unroll
            for (int rh = 0; rh < 2; rh++) {
                int b = rows[rh];
                int len = lenr[rh];
                float dtv = 0.0f;
                if (t + 1 < Lseq) dtv = ((t + 1) < len) ? dt[b * Lseq + t + 1] : 0.0f;
                float hn[2];
                #pragma unroll
                for (int cj = 0; cj < 2; cj++) {
                    int ci = rh * 2 + cj;
                    float i_g  = sigf(acc[0][ci]);
                    float f_g  = sigf(acc[1][ci]);
                    float ie_g = sigf(acc[2][ci]);
                    float fe_g = sigf(acc[3][ci]);
                    float o_n  = sigf(acc[4][ci]);
                    float z    = tanhf_fast(acc[5][ci]);
                    float d_n  = softplusf(acc[6][ci]);
                    float cs_n = f_g * stC[rh][cj] + i_g * z;
                    float ce_n = fe_g * stCe[rh][cj] + ie_g * z;
                    if (t == len - 1) {
                        float* f = out_final + (size_t)b * 4 * Dh + d0 + cj;
                        f[0 * Dh] = o_n;
                        f[1 * Dh] = cs_n;
                        f[2 * Dh] = ce_n;
                        f[3 * Dh] = d_n;
                    }
                    float cn = ce_n + (cs_n - ce_n) * __expf(-d_n * dtv);
                    float h = o_n * tanhf_fast(cn);
                    stC[rh][cj] = cn;
                    stCe[rh][cj] = ce_n;
                    hn[cj] = h;
                }
                if (t + 1 < Lseq) {
                    *(float2*)&out_h[((size_t)b * Lseq + (t + 1)) * Dh + d0] =
                        make_float2(hn[0], hn[1]);
                    g_H16[(t + 1) & 1][b * 256 + (d0 >> 1)] =
                        pack2h(__float2half_rn(hn[0]), __float2half_rn(hn[1]));
                }
            }
            if (t + 1 < Lseq) {
                // prefetch XP2[t+1] into acc (hidden behind barrier wait)
                const float* xb = g_xp2 + (((size_t)(t + 1) * 64 + dn) * 128) * 56;
                #pragma unroll
                for (int nt = 0; nt < 7; nt++) {
                    float2 x0 = *(const float2*)(xb + (size_t)rows[0] * 56 + nt * 8 + tq * 2);
                    float2 x1 = *(const float2*)(xb + (size_t)rows[1] * 56 + nt * 8 + tq * 2);
                    acc[nt][0] = x0.x; acc[nt][1] = x0.y;
                    acc[nt][2] = x1.x; acc[nt][3] = x1.y;
                }
                // wk0 warps (threads 0..63) sync, then single arrival
                asm volatile("bar.sync 1, 64;" ::: "memory");
                if (tid == 0) red_rel_add1(barp);   // publish h_{t+1}
            }
        }

        if (t + 1 < Lseq) {
            tgt += 128;
            if (tid == 0) { while (ld_acq(barp) < tgt) {} }
            __syncthreads();
        }
    }
}

// ---------------- launch ----------------
extern "C" void kernel_launch(void* const* d_in, const int* in_sizes, int n_in,
                              void* d_out, int out_size) {
    const float* x    = (const float*)d_in[0];   // (B,L,I)
    const float* dt   = (const float*)d_in[1];   // (B,L)
    const int*   sl   = (const int*)  d_in[2];   // (B,)
    const float* bos  = (const float*)d_in[3];   // (I,)
    const float* W    = (const float*)d_in[4];   // (7D, I+D)
    const float* bias = (const float*)d_in[5];   // (7D,)
    float* out = (float*)d_out;
    float* out_final = out + (size_t)Bsz * Lseq * Dh;

    cudaFuncSetAttribute(recur_kernel, cudaFuncAttributeMaxDynamicSharedMemorySize,
                         SMEM_RECUR);
    cudaFuncSetAttribute(xproj_hmma_kernel, cudaFuncAttributeMaxDynamicSharedMemorySize,
                         16384 * 4);

    prep_kernel<<<(ND + 255) / 256, 256>>>(bos, W, bias);
    pack_kernel<<<(XN2 + WN + 255) / 256, 256>>>(x, sl, W);
    xproj_hmma_kernel<<<dim3(28, 512), 256, 16384 * 4>>>(bias);
    recur_kernel<<<GRID_R, NTR, SMEM_RECUR>>>(W, dt, sl, out, out_final);
}

// round 17
// speedup vs baseline: 1.8659x; 1.0807x over previous
#include <cuda_runtime.h>
#include <cuda_fp16.h>
#include <math.h>
#include <stdint.h>

// Problem constants (ContTimeLSTM_66623532695635)
#define Bsz 128
#define Lseq 512
#define Iin 256
#define Dh 512
#define ND 3584          // 7*D
#define FIN 768          // I + D
#define BD (Bsz*Dh)      // 65536

#define GRID_R 128       // 64 dn x 2 bh; 1 block/SM (co-residency guaranteed)
#define NTR 512          // 16 warps: wm = w&3 (m16 group), wk = w>>2 (k quarter)

// ---------------- device scratch ----------------
__device__ uint32_t g_H16[2][BD / 2];                    // fp16 h, half2-packed
__device__ uint32_t g_x16[(size_t)Bsz * Lseq * Iin / 2]; // masked x, fp16 half2 [t*128+b][128]
__device__ float g_proj0[ND];
__device__ __align__(256) unsigned g_bar2[64];           // [0]: half 0, [32]: half 1

// ---- fast transcendentals (MUFU-based) ----
__device__ __forceinline__ float sigf(float x) {
    return __fdividef(1.0f, 1.0f + __expf(-x));
}
__device__ __forceinline__ float tanhf_fast(float x) {
    float xc = fminf(fmaxf(x, -15.0f), 15.0f);
    float e = __expf(2.0f * xc);
    return __fdividef(e - 1.0f, e + 1.0f);
}
__device__ __forceinline__ float softplusf(float x) {
    if (x > 0.0f) return x + __logf(1.0f + __expf(-x));
    return __logf(1.0f + __expf(x));
}
__device__ __forceinline__ unsigned ld_acq(unsigned* p) {
    unsigned v;
    asm volatile("ld.acquire.gpu.u32 %0, [%1];" : "=r"(v) : "l"(p) : "memory");
    return v;
}
__device__ __forceinline__ void red_rel_add1(unsigned* p) {
    asm volatile("red.release.gpu.global.add.u32 [%0], 1;" :: "l"(p) : "memory");
}
__device__ __forceinline__ uint32_t pack2h(__half a, __half b) {
    return ((uint32_t)__half_as_ushort(b) << 16) | __half_as_ushort(a);
}

#define MMA_F16(d, a, b0, b1) \
    asm volatile("mma.sync.aligned.m16n8k16.row.col.f32.f16.f16.f32 " \
        "{%0,%1,%2,%3}, {%4,%5,%6,%7}, {%8,%9}, {%0,%1,%2,%3};" \
        : "+f"((d)[0]), "+f"((d)[1]), "+f"((d)[2]), "+f"((d)[3]) \
        : "r"((a)[0]), "r"((a)[1]), "r"((a)[2]), "r"((a)[3]), "r"(b0), "r"(b1))

// ---------------- launch 1: reset barriers + proj0 ----------------
__global__ void prep_kernel(const float* __restrict__ bos,
                            const float* __restrict__ W,
                            const float* __restrict__ bias) {
    int n = blockIdx.x * blockDim.x + threadIdx.x;
    if (n == 0) { g_bar2[0] = 0u; g_bar2[32] = 0u; }
    if (n >= ND) return;
    const float* wrow = W + (size_t)n * FIN;
    float acc = bias[n];
    #pragma unroll 8
    for (int i = 0; i < Iin; i++) acc += bos[i] * wrow[i];
    g_proj0[n] = acc;
}

// ---------------- launch 2: pack x (masked, fp16 pairs) ----------------
#define XN2 (Bsz * Lseq * Iin / 2)     // 8,388,608 u32
__global__ void pack_kernel(const float* __restrict__ x,
                            const int* __restrict__ sl) {
    int idx = blockIdx.x * blockDim.x + threadIdx.x;
    if (idx >= XN2) return;
    int row = idx >> 7;
    int iu = idx & 127;
    int t = row >> 7;
    int b = row & 127;
    float v0 = 0.0f, v1 = 0.0f;
    if (t < __ldg(sl + b)) {
        const float* xp = x + ((size_t)b * Lseq + t) * Iin + iu * 2;
        v0 = xp[0]; v1 = xp[1];
    }
    g_x16[idx] = pack2h(__float2half_rn(v0), __float2half_rn(v1));
}

// ================= launch 3: fused persistent recurrence =================
// 128 blocks = 64 dn x 2 bh. 16 warps = 4 wm (m16) x 4 wk (k quarter).
// Per step: acc=bias -> x-part MMAs (no h dep, fills wait slack) -> barrier
// wait h_t -> h-part MMAs -> sRed reduce -> epilogue -> publish h_{t+1}.
#define NFRAG_H 224                  // 32 h-ks * 7 nt
#define NFRAG_X 112                  // 16 x-ks * 7 nt
#define SB_U32 ((NFRAG_H + NFRAG_X) * 64)   // 21504 u32 = 86016 B
#define RED_STRIDE 29                // odd stride -> conflict-free; SCALAR access
#define SRED_FLOATS (3 * 128 * RED_STRIDE)
#define SMEM_RECUR (SB_U32 * 4 + SRED_FLOATS * 4)   // 130560 B -> 1 block/SM

__global__ __launch_bounds__(NTR, 1)
void recur_kernel(const float* __restrict__ W,
                  const float* __restrict__ dt,
                  const int* __restrict__ sl,
                  const float* __restrict__ bias,
                  float* __restrict__ out_h,
                  float* __restrict__ out_final) {
    extern __shared__ uint32_t sB[];
    float* sRed = (float*)(sB + SB_U32);

    const int tid = threadIdx.x;
    const int w = tid >> 5;
    const int lane = tid & 31;
    const int g = lane >> 2;
    const int tq = lane & 3;
    const int wm = w & 3;            // m16 group (0..3)
    const int wk = w >> 2;           // k quarter (0..3)
    const int dn = blockIdx.x >> 1;
    const int bh = blockIdx.x & 1;
    const int d0 = dn * 8 + tq * 2;
    unsigned* barp = &g_bar2[bh * 32];

    // ---- pack W fragments (fp16): h-part frags [0,224), x-part frags [224,336) ----
    for (int e = tid; e < (NFRAG_H + NFRAG_X) * 32; e += NTR) {
        int f = e >> 5;
        int l = e & 31;
        int gg = l >> 2, tt = l & 3;
        int nt, koff;
        if (f < NFRAG_H) { nt = f % 7; koff = Iin + (f / 7) * 16; }
        else { int fx = f - NFRAG_H; nt = fx % 7; koff = (fx / 7) * 16; }
        int n = nt * Dh + dn * 8 + gg;
        const float* wr = W + (size_t)n * FIN + koff;
        __half h0 = __float2half_rn(wr[tt * 2]),     h1 = __float2half_rn(wr[tt * 2 + 1]);
        __half h2 = __float2half_rn(wr[tt * 2 + 8]), h3 = __float2half_rn(wr[tt * 2 + 9]);
        uint32_t* p = sB + (size_t)e * 2;
        p[0] = pack2h(h0, h1);
        p[1] = pack2h(h2, h3);
    }

    int rows[2];
    rows[0] = bh * 64 + wm * 16 + g;
    rows[1] = rows[0] + 8;

    int lenr[2] = {0, 0};
    float stC[2][2], stCe[2][2];
    float biasv[7][2];

    if (wk == 0) {
        #pragma unroll
        for (int nt = 0; nt < 7; nt++) {
            biasv[nt][0] = __ldg(bias + nt * Dh + d0);
            biasv[nt][1] = __ldg(bias + nt * Dh + d0 + 1);
        }
        #pragma unroll
        for (int rh = 0; rh < 2; rh++) {
            int b = rows[rh];
            lenr[rh] = sl[b];
            float dtv = dt[b * Lseq + 0];
            float h2v[2];
            #pragma unroll
            for (int cj = 0; cj < 2; cj++) {
                int d = d0 + cj;
                float p0 = g_proj0[0 * Dh + d];
                float p2 = g_proj0[2 * Dh + d];
                float p4 = g_proj0[4 * Dh + d];
                float p5 = g_proj0[5 * Dh + d];
                float p6 = g_proj0[6 * Dh + d];
                float z   = tanhf_fast(p5);
                float cs0 = sigf(p0) * z;
                float ce0 = sigf(p2) * z;
                float o0  = sigf(p4);
                float dn0 = softplusf(p6);
                float c = ce0 + (cs0 - ce0) * __expf(-dn0 * dtv);
                float h = o0 * tanhf_fast(c);
                stC[rh][cj] = c;
                stCe[rh][cj] = ce0;
                h2v[cj] = h;
            }
            *(float2*)&out_h[((size_t)b * Lseq + 0) * Dh + d0] = make_float2(h2v[0], h2v[1]);
            g_H16[0][b * 256 + (d0 >> 1)] =
                pack2h(__float2half_rn(h2v[0]), __float2half_rn(h2v[1]));
        }
    }

    __syncthreads();                         // sB + h0 stores ordered block-wide
    if (tid == 0) red_rel_add1(barp);        // 1 arrival/block -> 64/half
    unsigned tgt = 64;                       // wait consumed at t=0 inside loop

    const int kubase = wk * 64;              // h u32 index base for k quarter
    const int kxbase = wk * 32;              // x u32 index base (K=256 -> 128 u32)

    for (int t = 0; t < Lseq; t++) {
        // ---- acc init: bias (wk0) or zero ----
        float acc[7][4];
        if (wk == 0) {
            #pragma unroll
            for (int nt = 0; nt < 7; nt++) {
                acc[nt][0] = biasv[nt][0]; acc[nt][1] = biasv[nt][1];
                acc[nt][2] = biasv[nt][0]; acc[nt][3] = biasv[nt][1];
            }
        } else {
            #pragma unroll
            for (int nt = 0; nt < 7; nt++)
                #pragma unroll
                for (int ci = 0; ci < 4; ci++) acc[nt][ci] = 0.0f;
        }

        // ---- x-phase: no dependence on h_t; fills the barrier-wait slack ----
        {
            const uint32_t* xt0 = g_x16 + ((size_t)t * 128 + rows[0]) * 128;
            const uint32_t* xt1 = g_x16 + ((size_t)t * 128 + rows[1]) * 128;
            uint32_t ring[2][4];
            #pragma unroll
            for (int p = 0; p < 2; p++) {
                int ku = kxbase + p * 8 + tq;
                ring[p][0] = xt0[ku];
                ring[p][1] = xt1[ku];
                ring[p][2] = xt0[ku + 4];
                ring[p][3] = xt1[ku + 4];
            }
            #pragma unroll
            for (int ksx = 0; ksx < 4; ksx++) {
                int slot = ksx & 1;
                uint32_t a[4] = {ring[slot][0], ring[slot][1], ring[slot][2], ring[slot][3]};
                if (ksx + 2 < 4) {
                    int ku = kxbase + (ksx + 2) * 8 + tq;
                    ring[slot][0] = xt0[ku];
                    ring[slot][1] = xt1[ku];
                    ring[slot][2] = xt0[ku + 4];
                    ring[slot][3] = xt1[ku + 4];
                }
                int fx = NFRAG_H + (wk * 4 + ksx) * 7;
                #pragma unroll
                for (int nt = 0; nt < 7; nt++) {
                    uint2 bv = *(const uint2*)(sB + (size_t)((fx + nt) * 32 + lane) * 2);
                    MMA_F16(acc[nt], a, bv.x, bv.y);
                }
            }
        }

        // ---- barrier: h_t published by all blocks of this half ----
        if (tid == 0) { while (ld_acq(barp) < tgt) {} }
        __syncthreads();                     // broadcast + sRed reuse protection

        // ---- h-phase ----
        {
            const uint32_t* Hs = g_H16[t & 1];
            const uint32_t* h0p = Hs + rows[0] * 256;
            const uint32_t* h1p = Hs + rows[1] * 256;
            uint32_t ring[2][4];
            #pragma unroll
            for (int p = 0; p < 2; p++) {
                int ku = kubase + p * 8 + tq;
                ring[p][0] = h0p[ku];
                ring[p][1] = h1p[ku];
                ring[p][2] = h0p[ku + 4];
                ring[p][3] = h1p[ku + 4];
            }
            #pragma unroll 4
            for (int ks = 0; ks < 8; ks++) {
                int slot = ks & 1;
                uint32_t a[4] = {ring[slot][0], ring[slot][1], ring[slot][2], ring[slot][3]};
                if (ks + 2 < 8) {
                    int ku = kubase + (ks + 2) * 8 + tq;
                    ring[slot][0] = h0p[ku];
                    ring[slot][1] = h1p[ku];
                    ring[slot][2] = h0p[ku + 4];
                    ring[slot][3] = h1p[ku + 4];
                }
                int fh = (wk * 8 + ks) * 7;
                #pragma unroll
                for (int nt = 0; nt < 7; nt++) {
                    uint2 bv = *(const uint2*)(sB + (size_t)((fh + nt) * 32 + lane) * 2);
                    MMA_F16(acc[nt], a, bv.x, bv.y);
                }
            }
        }

        if (wk != 0) {
            float* rp = sRed + (size_t)(((wk - 1) * 128) + wm * 32 + lane) * RED_STRIDE;
            #pragma unroll
            for (int nt = 0; nt < 7; nt++) {
                rp[nt * 4 + 0] = acc[nt][0];
                rp[nt * 4 + 1] = acc[nt][1];
                rp[nt * 4 + 2] = acc[nt][2];
                rp[nt * 4 + 3] = acc[nt][3];
            }
        }
        __syncthreads();                     // sRed visible

        if (wk == 0) {
            #pragma unroll
            for (int q = 0; q < 3; q++) {
                const float* rp = sRed + (size_t)(q * 128 + wm * 32 + lane) * RED_STRIDE;
                #pragma unroll
                for (int nt = 0; nt < 7; nt++) {
                    acc[nt][0] += rp[nt * 4 + 0];
                    acc[nt][1] += rp[nt * 4 + 1];
                    acc[nt][2] += rp[nt * 4 + 2];
                    acc[nt][3] += rp[nt * 4 + 3];
                }
            }
            // ---- epilogue: gates + state for 2 rows x 2 d ----
            #pragma unroll
            for (int rh = 0; rh < 2; rh++) {
                int b = rows[rh];
                int len = lenr[rh];
                float dtv = 0.0f;
                if (t + 1 < Lseq) dtv = ((t + 1) < len) ? dt[b * Lseq + t + 1] : 0.0f;
                float hn[2];
                #pragma unroll
                for (int cj = 0; cj < 2; cj++) {
                    int ci = rh * 2 + cj;
                    float i_g  = sigf(acc[0][ci]);
                    float f_g  = sigf(acc[1][ci]);
                    float ie_g = sigf(acc[2][ci]);
                    float fe_g = sigf(acc[3][ci]);
                    float o_n  = sigf(acc[4][ci]);
                    float z    = tanhf_fast(acc[5][ci]);
                    float d_n  = softplusf(acc[6][ci]);
                    float cs_n = f_g * stC[rh][cj] + i_g * z;
                    float ce_n = fe_g * stCe[rh][cj] + ie_g * z;
                    if (t == len - 1) {
                        float* f = out_final + (size_t)b * 4 * Dh + d0 + cj;
                        f[0 * Dh] = o_n;
                        f[1 * Dh] = cs_n;
                        f[2 * Dh] = ce_n;
                        f[3 * Dh] = d_n;
                    }
                    float cn = ce_n + (cs_n - ce_n) * __expf(-d_n * dtv);
                    float h = o_n * tanhf_fast(cn);
                    stC[rh][cj] = cn;
                    stCe[rh][cj] = ce_n;
                    hn[cj] = h;
                }
                if (t + 1 < Lseq) {
                    *(float2*)&out_h[((size_t)b * Lseq + (t + 1)) * Dh + d0] =
                        make_float2(hn[0], hn[1]);
                    g_H16[(t + 1) & 1][b * 256 + (d0 >> 1)] =
                        pack2h(__float2half_rn(hn[0]), __float2half_rn(hn[1]));
                }
            }
            if (t + 1 < Lseq) {
                // wk0 warps (threads 0..127) sync, then single arrival
                asm volatile("bar.sync 1, 128;" ::: "memory");
                if (tid == 0) red_rel_add1(barp);   // publish h_{t+1}
            }
        }
        tgt += 64;   // next iteration's wait target
    }
}

// ---------------- launch ----------------
extern "C" void kernel_launch(void* const* d_in, const int* in_sizes, int n_in,
                              void* d_out, int out_size) {
    const float* x    = (const float*)d_in[0];   // (B,L,I)
    const float* dt   = (const float*)d_in[1];   // (B,L)
    const int*   sl   = (const int*)  d_in[2];   // (B,)
    const float* bos  = (const float*)d_in[3];   // (I,)
    const float* W    = (const float*)d_in[4];   // (7D, I+D)
    const float* bias = (const float*)d_in[5];   // (7D,)
    float* out = (float*)d_out;
    float* out_final = out + (size_t)Bsz * Lseq * Dh;

    cudaFuncSetAttribute(recur_kernel, cudaFuncAttributeMaxDynamicSharedMemorySize,
                         SMEM_RECUR);

    prep_kernel<<<(ND + 255) / 256, 256>>>(bos, W, bias);
    pack_kernel<<<(XN2 + 255) / 256, 256>>>(x, sl);
    recur_kernel<<<GRID_R, NTR, SMEM_RECUR>>>(W, dt, sl, bias, out, out_final);
}